// round 10
// baseline (speedup 1.0000x reference)
#include <cuda_runtime.h>
#include <cuda_bf16.h>
#include <math.h>
#include <stdint.h>

#define NENT 50000
#define MTILES 391
#define NEDGE 400000
#define NCSR  (2*NEDGE)
#define BQ 32
#define HID 128
#define G4 512
#define NB_SCAN 49

// ---------------- scratch (device globals; no allocation) ----------------
__device__ __align__(16) float g_Ppre[2*25*G4];
__device__ __align__(16) float g_hF[NENT*HID];
__device__ __align__(16) float g_hB[NENT*HID];
__device__ float g_eattn[NENT*24];
__device__ __align__(16) float g_Wqperm[6*G4*HID];
__device__ __align__(16) float g_Pq[6*BQ*G4];
__device__ __align__(16) float g_qh[18*BQ*HID];
__device__ float g_qc[6*BQ*HID];
__device__ float g_qattn[9*BQ*25];
__device__ float g_bufA[3*NENT*BQ];
__device__ float g_bufB[3*NENT*BQ];
__device__ float g_sumsA[96];
__device__ float g_sumsB[96];

// CSR over targets (fwd+rev entries)
__device__ int  g_cnt[NENT];
__device__ int  g_offs[NENT+1];
__device__ int  g_fill[NENT];
__device__ int  g_bsum[64];
__device__ int  g_wind[NCSR];               // immutable weight-index per entry
__device__ __align__(8) int2 g_csr[NCSR];   // .x = src | (rei<<17), .y = weight bits (refreshed each call)

// B operands (bf16 hi only): [dir(2)][p 512 (perm gate col)][k 128]
__device__ __align__(16) __nv_bfloat16 g_Bmma[2*512*128];

// HW tanh (sm_75+): single MUFU op; sigmoid via identity
__device__ __forceinline__ float htanh(float x){
    float y; asm("tanh.approx.f32 %0, %1;" : "=f"(y) : "f"(x)); return y;
}
__device__ __forceinline__ float hsigm(float x){
    return fmaf(htanh(0.5f*x), 0.5f, 0.5f);
}

__device__ __forceinline__ uint32_t smem_u32(const void* p){
    uint32_t a;
    asm("{ .reg .u64 t; cvta.to.shared.u64 t, %1; cvt.u32.u64 %0, t; }" : "=r"(a) : "l"(p));
    return a;
}

#define LDSM4(r, addr) \
    asm volatile("ldmatrix.sync.aligned.m8n8.x4.shared.b16 {%0,%1,%2,%3}, [%4];" \
        : "=r"((r)[0]),"=r"((r)[1]),"=r"((r)[2]),"=r"((r)[3]) : "r"(addr))

#define MMA16816(d, a, b0, b1) \
    asm volatile("mma.sync.aligned.m16n8k16.row.col.f32.bf16.bf16.f32 " \
        "{%0,%1,%2,%3}, {%4,%5,%6,%7}, {%8,%9}, {%0,%1,%2,%3};" \
        : "+f"((d)[0]),"+f"((d)[1]),"+f"((d)[2]),"+f"((d)[3]) \
        : "r"((a)[0]),"r"((a)[1]),"r"((a)[2]),"r"((a)[3]), "r"(b0),"r"(b1))

#define CPA16(dst, src) asm volatile("cp.async.cg.shared.global [%0], [%1], 16;" :: "r"(dst), "l"(src))
#define CPA_COMMIT()    asm volatile("cp.async.commit_group;" ::: "memory")
#define CPA_WAIT0()     asm volatile("cp.async.wait_group 0;" ::: "memory")

#define SM_A   131072
#define DSMEM  196608

// ---------------- preprocessing ----------------
#define S2 25600
#define S4 393216
#define S5 98304
#define S6 131072
#define PREP_TOT (S2+S4+S5+S6)

__global__ void prep_kernel(const float* __restrict__ eWih, const float* __restrict__ eWhh,
                            const float* __restrict__ ebih, const float* __restrict__ ebhh,
                            const float* __restrict__ eemb,
                            const float* __restrict__ qWih, const float* __restrict__ qWhh,
                            const float* __restrict__ qbih, const float* __restrict__ qbhh,
                            const float* __restrict__ qemb, const int* __restrict__ queries){
    int idx = blockIdx.x*blockDim.x + threadIdx.x;
    if (idx < S2){
        int dir = idx / 12800; int rem = idx % 12800; int v = rem >> 9; int p = rem & 511;
        int j = ((p&3)<<7) + (p>>2);
        float acc = ebih[(dir<<9)+j] + ebhh[(dir<<9)+j];
        const float* wr = eWih + (dir<<16) + (j<<7);
        const float* er = eemb + (v<<7);
        for (int k=0;k<128;k++) acc += er[k]*wr[k];
        g_Ppre[(dir*12800) + (v<<9) + p] = acc;
        return;
    }
    idx -= S2;
    if (idx < S4){
        int pr = idx >> 16; int rem = idx & 65535; int p = rem >> 7; int k = rem & 127;
        int j = ((p&3)<<7) + (p>>2);
        g_Wqperm[idx] = qWhh[(pr<<16) + (j<<7) + k];
        return;
    }
    idx -= S4;
    if (idx < S5){
        int pr = idx >> 14; int rem = idx & 16383; int b = rem >> 9; int p = rem & 511;
        int j = ((p&3)<<7) + (p>>2);
        float acc = qbih[(pr<<9)+j] + qbhh[(pr<<9)+j];
        const float* wr = qWih + (pr<<16) + (j<<7);
        const float* xr = qemb + (queries[b]<<7);
        for (int k=0;k<128;k++) acc += xr[k]*wr[k];
        g_Pq[(pr<<14) + (b<<9) + p] = acc;
        return;
    }
    idx -= S5;
    if (idx < S6){
        int dir = idx >> 16;
        int p = (idx >> 7) & 511;
        int k = idx & 127;
        int q = p & 15, b = p >> 4;
        int u = 4*b + ((q&7)>>1);
        int gate = (q<8) ? (q&1) : 2+(q&1);
        int j = (gate<<7) + u;
        g_Bmma[idx] = __float2bfloat16(eWhh[(dir<<16) + (j<<7) + k]);
    }
}

// ---------------- CSR build ----------------
__global__ void zero_cnt(){
    int i = blockIdx.x*blockDim.x + threadIdx.x;
    if (i < NENT) g_cnt[i] = 0;
}
__global__ void count_k(const int* __restrict__ th, const int* __restrict__ tt){
    int e = blockIdx.x*blockDim.x + threadIdx.x;
    if (e >= NEDGE) return;
    atomicAdd(&g_cnt[tt[e]], 1);
    atomicAdd(&g_cnt[th[e]], 1);
}
__global__ void scan1(){
    __shared__ int sh[1024];
    int i = blockIdx.x*1024 + threadIdx.x;
    int v = (i<NENT)? g_cnt[i] : 0;
    sh[threadIdx.x]=v;
    __syncthreads();
    for (int off=1; off<1024; off<<=1){
        int t = (threadIdx.x>=off)? sh[threadIdx.x-off] : 0;
        __syncthreads();
        sh[threadIdx.x]+=t;
        __syncthreads();
    }
    if (i<NENT) g_offs[i] = sh[threadIdx.x]-v;
    if (threadIdx.x==1023) g_bsum[blockIdx.x]=sh[1023];
}
__global__ void scan2(){
    __shared__ int sh[64];
    int v = (threadIdx.x<NB_SCAN)? g_bsum[threadIdx.x] : 0;
    sh[threadIdx.x]=v;
    __syncthreads();
    for (int off=1; off<64; off<<=1){
        int t = (threadIdx.x>=off)? sh[threadIdx.x-off] : 0;
        __syncthreads();
        sh[threadIdx.x]+=t;
        __syncthreads();
    }
    if (threadIdx.x<NB_SCAN) g_bsum[threadIdx.x] = sh[threadIdx.x]-v;
    if (threadIdx.x==NB_SCAN-1) g_bsum[63] = sh[NB_SCAN-1];
}
__global__ void scan3(){
    int i = blockIdx.x*blockDim.x + threadIdx.x;
    if (i<NENT){
        int v = g_offs[i] + g_bsum[i>>10];
        g_offs[i]=v;
        g_fill[i]=v;
    }
    if (i==0) g_offs[NENT] = g_bsum[63];
}
__global__ void scatter_k(const int* __restrict__ rl, const int* __restrict__ th,
                          const int* __restrict__ tt){
    int e = blockIdx.x*blockDim.x + threadIdx.x;
    if (e >= NEDGE) return;
    int h = th[e], t2 = tt[e], r = rl[e];
    int wind = h*24 + r;
    int p1 = atomicAdd(&g_fill[t2], 1);
    g_csr[p1].x = h | (r<<17);
    g_wind[p1] = wind;
    int p2 = atomicAdd(&g_fill[h], 1);
    g_csr[p2].x = t2 | ((r+12)<<17);
    g_wind[p2] = wind;
}
__global__ void fill_w(){
    int i = blockIdx.x*blockDim.x + threadIdx.x;
    if (i >= NCSR) return;
    g_csr[i].y = __float_as_int(g_eattn[g_wind[i]]);
}

// ---------------- fused entity BiLSTM ----------------
__global__ __launch_bounds__(512) void ent_fused(const int* __restrict__ degs){
    extern __shared__ __align__(16) char sm[];
    uint32_t sb = smem_u32(sm);
    int tid = threadIdx.x, lane = tid&31, wid = tid>>5;
    int warpM = wid&3, warpN = (wid>>2)&3;
    int mt = blockIdx.x, dir = blockIdx.y;
    int mbase = mt*128;

    #pragma unroll
    for (int j=0;j<16;j++){
        int i = tid + (j<<9);
        int p = i>>4, c = i&15;
        uint32_t dst = sb + ((p>>7)<<15) + ((p&127)<<8) + (((c ^ (p&7)))<<4);
        const void* src = g_Bmma + ((size_t)(dir<<9) + p)*128 + c*8;
        CPA16(dst, src);
    }
    CPA_COMMIT();

    int tg = lane>>2, tc = lane&3;
    int rows[4];
    #pragma unroll
    for (int mi=0;mi<2;mi++)
        #pragma unroll
        for (int rh=0;rh<2;rh++)
            rows[mi*2+rh] = warpM*32 + mi*16 + rh*8 + tg;

    float c_reg[4][8];
    uint32_t hp[4][8];
    const float* Pdir = g_Ppre + dir*12800;
    float* gH = dir ? g_hB : g_hF;

    {
        int t0 = dir ? 7 : 0;
        #pragma unroll
        for (int r4=0;r4<4;r4++){
            int row = rows[r4];
            int m = mbase + row;
            bool mv = (m < NENT);
            int d = mv ? degs[(m<<3)+t0] : 0;
            const float4* Pb = (const float4*)(Pdir + (d<<9));
            #pragma unroll
            for (int ch=0;ch<4;ch++){
                #pragma unroll
                for (int nt2=0;nt2<2;nt2++){
                    int u = ch*32 + warpN*8 + nt2*4 + tc;
                    float4 P = Pb[u];
                    float cn = hsigm(P.x)*htanh(P.z);
                    float h  = hsigm(P.w)*htanh(cn);
                    c_reg[ch][r4*2+nt2] = cn;
                    __nv_bfloat16 hh = __float2bfloat16(h);
                    __nv_bfloat16 hl = __float2bfloat16(h - __bfloat162float(hh));
                    uint32_t off = (row<<8) + ((((u>>3) ^ (row&7)))<<4) + ((u&7)<<1);
                    *(__nv_bfloat16*)(sm + SM_A + off) = hh;
                    *(__nv_bfloat16*)(sm + SM_A + 32768 + off) = hl;
                }
            }
        }
    }
    CPA_WAIT0();
    __syncthreads();

    int aRowBase = warpM*32 + (lane&7) + ((lane>>3)&1)*8;
    int aHi = lane>>4;
    int bRowBase = warpN*32 + (lane&7) + (lane>>4)*8;
    int bHi = (lane>>3)&1;

    #pragma unroll 1
    for (int s=1;s<8;s++){
        int t = dir ? 7-s : s;
        #pragma unroll
        for (int ch=0;ch<4;ch++){
            float acc[2][4][4] = {};
            uint32_t bP = sb + (ch<<15);
            // merged hi/lo passes: B fragments loaded once, reused for both A planes
            #pragma unroll
            for (int kc=0;kc<8;kc++){
                uint32_t bfr[2][4], ah[2][4], al[2][4];
                #pragma unroll
                for (int nt2=0;nt2<2;nt2++){
                    int rb = bRowBase + nt2*16;
                    LDSM4(bfr[nt2], bP + (rb<<8) + (((2*kc + bHi) ^ (rb&7))<<4));
                }
                #pragma unroll
                for (int mi=0;mi<2;mi++){
                    int ra = aRowBase + mi*16;
                    uint32_t colsw = (uint32_t)(((2*kc + aHi) ^ (ra&7))<<4);
                    LDSM4(ah[mi], sb + SM_A + (ra<<8) + colsw);
                    LDSM4(al[mi], sb + SM_A + 32768 + (ra<<8) + colsw);
                }
                #pragma unroll
                for (int mi=0;mi<2;mi++)
                    #pragma unroll
                    for (int nt2=0;nt2<2;nt2++){
                        MMA16816(acc[mi][2*nt2],   ah[mi], bfr[nt2][0], bfr[nt2][1]);
                        MMA16816(acc[mi][2*nt2+1], ah[mi], bfr[nt2][2], bfr[nt2][3]);
                        MMA16816(acc[mi][2*nt2],   al[mi], bfr[nt2][0], bfr[nt2][1]);
                        MMA16816(acc[mi][2*nt2+1], al[mi], bfr[nt2][2], bfr[nt2][3]);
                    }
            }
            #pragma unroll
            for (int mi=0;mi<2;mi++){
                #pragma unroll
                for (int rh=0;rh<2;rh++){
                    int r4 = mi*2+rh;
                    int row = rows[r4];
                    int m = mbase + row;
                    bool mv = (m < NENT);
                    int d = mv ? degs[(m<<3)+t] : 0;
                    const float4* Pb = (const float4*)(Pdir + (d<<9));
                    #pragma unroll
                    for (int nt2=0;nt2<2;nt2++){
                        int u = ch*32 + warpN*8 + nt2*4 + tc;
                        float4 P = Pb[u];
                        float ig = hsigm(acc[mi][2*nt2  ][rh*2+0] + P.x);
                        float fg = hsigm(acc[mi][2*nt2  ][rh*2+1] + P.y);
                        float gg = htanh(acc[mi][2*nt2+1][rh*2+0] + P.z);
                        float og = hsigm(acc[mi][2*nt2+1][rh*2+1] + P.w);
                        float cn = fg*c_reg[ch][r4*2+nt2] + ig*gg;
                        c_reg[ch][r4*2+nt2] = cn;
                        float h = og*htanh(cn);
                        if (s==7){
                            if (mv) gH[(m<<7)+u] = h;
                        } else {
                            __nv_bfloat16 hh = __float2bfloat16(h);
                            __nv_bfloat16 hl = __float2bfloat16(h - __bfloat162float(hh));
                            hp[ch][r4*2+nt2] = (uint32_t)__bfloat16_as_ushort(hh)
                                             | ((uint32_t)__bfloat16_as_ushort(hl)<<16);
                        }
                    }
                }
            }
        }
        if (s<7){
            __syncthreads();
            #pragma unroll
            for (int ch=0;ch<4;ch++){
                #pragma unroll
                for (int r4=0;r4<4;r4++){
                    int row = rows[r4];
                    #pragma unroll
                    for (int nt2=0;nt2<2;nt2++){
                        int u = ch*32 + warpN*8 + nt2*4 + tc;
                        uint32_t v = hp[ch][r4*2+nt2];
                        uint32_t off = (row<<8) + ((((u>>3) ^ (row&7)))<<4) + ((u&7)<<1);
                        *(uint16_t*)(sm + SM_A + off) = (uint16_t)(v & 0xffffu);
                        *(uint16_t*)(sm + SM_A + 32768 + off) = (uint16_t)(v >> 16);
                    }
                }
            }
            __syncthreads();
        }
    }
}

// ---------------- entity attention ----------------
__global__ void ent_attn_kernel(const float* __restrict__ W, const float* __restrict__ bias){
    __shared__ float Ws[8192];
    int tid = threadIdx.x;
    for (int i=tid;i<8192;i+=256) Ws[i]=0.f;
    __syncthreads();
    for (int i=tid;i<24*256;i+=256){ int o=i>>8, k=i&255; Ws[(k<<5)+o]=W[i]; }
    __syncthreads();
    int lane = tid&31;
    int wid = (blockIdx.x<<3) + (tid>>5);
    int nw  = gridDim.x<<3;
    float bv = (lane<24)? bias[lane] : -1e30f;
    for (int n=wid; n<NENT; n+=nw){
        float acc = bv;
        const float* hf = g_hF + (n<<7);
        const float* hb = g_hB + (n<<7);
        for (int k=0;k<128;k++) acc += hf[k]*Ws[(k<<5)+lane];
        for (int k=0;k<128;k++) acc += hb[k]*Ws[((k+128)<<5)+lane];
        float mx = acc;
        for (int o=16;o;o>>=1) mx = fmaxf(mx, __shfl_xor_sync(0xffffffffu, mx, o));
        float e = (lane<24)? expf(acc-mx) : 0.f;
        float s = e;
        for (int o=16;o;o>>=1) s += __shfl_xor_sync(0xffffffffu, s, o);
        if (lane<24) g_eattn[n*24+lane] = e/s;
    }
}

// ---------------- query LSTMs ----------------
__global__ void q_step0(){
    int idx = blockIdx.x*blockDim.x + threadIdx.x;
    if (idx >= 6*BQ*HID) return;
    int pr = idx/4096; int rem = idx&4095; int b = rem>>7; int u = rem&127;
    float4 P = *(const float4*)(g_Pq + (pr<<14) + (b<<9) + (u<<2));
    float cn = hsigm(P.x)*htanh(P.z);
    g_qc[idx] = cn;
    g_qh[pr*3*4096 + rem] = hsigm(P.w)*htanh(cn);
}

__global__ __launch_bounds__(256) void q_step(int s){
    int pr = blockIdx.y;
    int cb = blockIdx.x<<6;
    const float* h_in = g_qh + (pr*3 + s-1)*4096;
    float* h_out      = g_qh + (pr*3 + s)*4096;
    __shared__ float As[16][36];
    __shared__ float Bs[16][68];
    int tid=threadIdx.x;
    int ty=tid>>4, tx=tid&15;
    const float* Wp = g_Wqperm + (pr<<16);
    float acc[2][4] = {};
    int lrA = tid>>3; int kqA = (tid&7)<<1;
    int lrB = tid>>2; int kqB = (tid&3)<<2;
    for (int kb=0;kb<128;kb+=16){
        float2 a2 = *(const float2*)(h_in + (lrA<<7) + kb + kqA);
        float4 b4 = *(const float4*)(Wp + ((cb+lrB)<<7) + kb + kqB);
        As[kqA+0][lrA]=a2.x; As[kqA+1][lrA]=a2.y;
        Bs[kqB+0][lrB]=b4.x; Bs[kqB+1][lrB]=b4.y; Bs[kqB+2][lrB]=b4.z; Bs[kqB+3][lrB]=b4.w;
        __syncthreads();
        #pragma unroll
        for (int k=0;k<16;k++){
            float a0=As[k][(ty<<1)], a1=As[k][(ty<<1)+1];
            float4 b=*(const float4*)&Bs[k][tx<<2];
            acc[0][0]+=a0*b.x; acc[0][1]+=a0*b.y; acc[0][2]+=a0*b.z; acc[0][3]+=a0*b.w;
            acc[1][0]+=a1*b.x; acc[1][1]+=a1*b.y; acc[1][2]+=a1*b.z; acc[1][3]+=a1*b.w;
        }
        __syncthreads();
    }
    int u = (cb>>2)+tx;
    #pragma unroll
    for (int i=0;i<2;i++){
        int b = (ty<<1)+i;
        float4 P = *(const float4*)(g_Pq + (pr<<14) + (b<<9) + cb + (tx<<2));
        float ig=hsigm(acc[i][0]+P.x), fg=hsigm(acc[i][1]+P.y);
        float gg=htanh(acc[i][2]+P.z), og=hsigm(acc[i][3]+P.w);
        int ci = pr*4096 + (b<<7) + u;
        float cn = fg*g_qc[ci] + ig*gg;
        g_qc[ci]=cn;
        h_out[(b<<7)+u]=og*htanh(cn);
    }
}

__global__ void q_attn_kernel(const float* __restrict__ W, const float* __restrict__ bias){
    __shared__ float Ws[8192];
    int tid=threadIdx.x;
    for (int i=tid;i<8192;i+=256) Ws[i]=0.f;
    __syncthreads();
    for (int i=tid;i<25*256;i+=256){ int o=i>>8,k=i&255; Ws[(k<<5)+o]=W[i]; }
    __syncthreads();
    int lane=tid&31;
    int gw=(blockIdx.x<<3)+(tid>>5);
    if (gw>=288) return;
    int b=gw&31, rt=gw>>5; int r=rt/3, t=rt%3;
    const float* hf = g_qh + ((r*2  )*3 + t    )*4096 + (b<<7);
    const float* hb = g_qh + ((r*2+1)*3 + (2-t))*4096 + (b<<7);
    float acc = (lane<25)? bias[lane] : -1e30f;
    for (int k=0;k<128;k++) acc += hf[k]*Ws[(k<<5)+lane];
    for (int k=0;k<128;k++) acc += hb[k]*Ws[((k+128)<<5)+lane];
    float mx=acc;
    for (int o=16;o;o>>=1) mx=fmaxf(mx,__shfl_xor_sync(0xffffffffu,mx,o));
    float e=(lane<25)?expf(acc-mx):0.f;
    float s=e;
    for (int o=16;o;o>>=1) s+=__shfl_xor_sync(0xffffffffu,s,o);
    if (lane<25) g_qattn[rt*800 + b*25 + lane] = e/s;
}

// ---------------- propagation (CSR gather + fused colsum) ----------------
__global__ void init_sums(){
    int i = threadIdx.x;
    if (i<96){ g_sumsA[i]=1.f; g_sumsB[i]=0.f; }
}

// ab=0: in=bufA/sumsA, out=bufB, colsum->sumsB ; ab=1: in=bufB/sumsB, out=bufA, colsum->sumsA
// t0flag: step-0 input is the one-hot memory (heads) — no buffer reads at all.
__global__ __launch_bounds__(256) void csr_step(int ab, int t, int t0flag,
                                                const int* __restrict__ heads){
    int r = blockIdx.y;
    __shared__ float qs[800];
    const float* qa = g_qattn + (r*3+t)*800;
    for (int i=threadIdx.x;i<800;i+=256) qs[i]=qa[i];
    __syncthreads();
    const float* inb  = (ab ? g_bufB : g_bufA) + r*NENT*BQ;
    float*       outb = (ab ? g_bufA : g_bufB) + r*NENT*BQ;
    const float* sums =  ab ? g_sumsB : g_sumsA;
    float*       osum =  ab ? g_sumsA : g_sumsB;
    int lane = threadIdx.x&31, wid = threadIdx.x>>5;
    float inv = __fdividef(1.f, fmaxf(1e-20f, sums[r*32+lane]));
    float qlast = qs[lane*25+24];
    int hb = t0flag ? heads[lane] : 0;
    float csum = 0.f;
    int n0 = (blockIdx.x<<6) + (wid<<3);
    #pragma unroll 1
    for (int j=0;j<8;j++){
        int n = n0+j;
        if (n < NENT){
            float acc;
            int s0 = g_offs[n], s1 = g_offs[n+1];
            if (t0flag){
                acc = qlast * ((hb==n)? 1.f : 0.f);
                for (int i=s0;i<s1;i++){
                    int2 en = g_csr[i];
                    float val = qs[lane*25 + (en.x>>17)] * __int_as_float(en.y);
                    acc += ((en.x & 0x1FFFF)==hb) ? val : 0.f;
                }
            } else {
                acc = qlast * inb[(n<<5)+lane];
                for (int i=s0;i<s1;i++){
                    int2 en = g_csr[i];
                    float val = qs[lane*25 + (en.x>>17)] * __int_as_float(en.y);
                    acc += val * inb[((en.x & 0x1FFFF)<<5) + lane];
                }
            }
            float v = acc*inv;
            outb[(n<<5)+lane] = v;
            csum += v;
        }
    }
    __shared__ float sh[8][32];
    sh[wid][lane]=csum;
    __syncthreads();
    if (wid==0){
        float s=0.f;
        #pragma unroll
        for (int i=0;i<8;i++) s+=sh[i][lane];
        atomicAdd(&osum[r*32+lane], s);
    }
}

__global__ void zero_sums(int sel){
    if (threadIdx.x < 96) (sel ? g_sumsB : g_sumsA)[threadIdx.x] = 0.f;
}

__global__ void trans_out(float* __restrict__ out){
    __shared__ float tile[32][33];
    __shared__ float invs[96];
    int tx=threadIdx.x, ty=threadIdx.y;
    if (ty<3) invs[ty*32+tx] = __fdividef(1.f, fmaxf(1e-20f, g_sumsB[ty*32+tx]));
    __syncthreads();
    int n0=blockIdx.x<<5;
    int n=n0+ty;
    float v = 0.f;
    if (n<NENT){
        int i = (n<<5)+tx;
        v = g_bufB[i]*invs[tx] + g_bufB[NENT*BQ+i]*invs[32+tx] + g_bufB[2*NENT*BQ+i]*invs[64+tx];
    }
    tile[ty][tx] = v;
    __syncthreads();
    int nn=n0+tx;
    if (nn<NENT) out[ty*NENT+nn] = tile[tx][ty];
}

// ---------------- host ----------------
extern "C" void kernel_launch(void* const* d_in, const int* in_sizes, int n_in,
                              void* d_out, int out_size){
    const int*   queries=(const int*)d_in[0];
    const int*   heads  =(const int*)d_in[1];
    const int*   rels   =(const int*)d_in[2];
    const int*   t_heads=(const int*)d_in[3];
    const int*   t_tails=(const int*)d_in[4];
    const int*   degs   =(const int*)d_in[5];
    const float* qemb=(const float*)d_in[6];
    const float* eemb=(const float*)d_in[7];
    const float* qWih=(const float*)d_in[8];
    const float* qWhh=(const float*)d_in[9];
    const float* qbih=(const float*)d_in[10];
    const float* qbhh=(const float*)d_in[11];
    const float* eWih=(const float*)d_in[12];
    const float* eWhh=(const float*)d_in[13];
    const float* ebih=(const float*)d_in[14];
    const float* ebhh=(const float*)d_in[15];
    const float* qlW=(const float*)d_in[16];
    const float* qlb=(const float*)d_in[17];
    const float* elW=(const float*)d_in[18];
    const float* elb=(const float*)d_in[19];
    float* out=(float*)d_out;

    cudaFuncSetAttribute(ent_fused, cudaFuncAttributeMaxDynamicSharedMemorySize, DSMEM);

    prep_kernel<<<(PREP_TOT+255)/256,256>>>(eWih,eWhh,ebih,ebhh,eemb,
                                            qWih,qWhh,qbih,qbhh,qemb,queries);
    // CSR build (rebuilt every call; deterministic given inputs)
    zero_cnt<<<(NENT+255)/256,256>>>();
    count_k<<<(NEDGE+255)/256,256>>>(t_heads, t_tails);
    scan1<<<NB_SCAN,1024>>>();
    scan2<<<1,64>>>();
    scan3<<<(NENT+255)/256,256>>>();
    scatter_k<<<(NEDGE+255)/256,256>>>(rels, t_heads, t_tails);

    // entity BiLSTM: all 8 steps, both directions, one launch
    ent_fused<<<dim3(MTILES,2),512,DSMEM>>>(degs);

    ent_attn_kernel<<<1024,256>>>(elW, elb);
    fill_w<<<(NCSR+255)/256,256>>>();

    // query BiLSTMs
    q_step0<<<96,256>>>();
    q_step<<<dim3(8,6),256>>>(1);
    q_step<<<dim3(8,6),256>>>(2);
    q_attn_kernel<<<36,256>>>(qlW, qlb);

    // propagation: 3 ranks per launch; colsum fused; t=0 one-hot (no buffer init)
    init_sums<<<1,128>>>();
    csr_step<<<dim3(782,3),256>>>(0, 0, 1, heads);   // one-hot -> bufB, colsum -> sumsB
    zero_sums<<<1,128>>>(0);
    csr_step<<<dim3(782,3),256>>>(1, 1, 0, heads);   // bufB -> bufA, colsum -> sumsA
    zero_sums<<<1,128>>>(1);
    csr_step<<<dim3(782,3),256>>>(0, 2, 0, heads);   // bufA -> bufB, colsum -> sumsB
    trans_out<<<1563,dim3(32,32)>>>(out);
}

// round 11
// speedup vs baseline: 1.4676x; 1.4676x over previous
#include <cuda_runtime.h>
#include <cuda_bf16.h>
#include <math.h>
#include <stdint.h>

#define NENT 50000
#define MTILES 391
#define NEDGE 400000
#define NCSR  (2*NEDGE)
#define BQ 32
#define HID 128
#define G4 512
#define NB_SCAN 49

// ---------------- scratch (device globals; no allocation) ----------------
__device__ __align__(16) float g_Ppre[2*25*G4];
__device__ __align__(16) float g_hF[NENT*HID];
__device__ __align__(16) float g_hB[NENT*HID];
__device__ float g_eattn[NENT*24];
__device__ __align__(16) float g_Wqperm[6*G4*HID];
__device__ __align__(16) float g_Pq[6*BQ*G4];
__device__ __align__(16) float g_qh[18*BQ*HID];
__device__ float g_qc[6*BQ*HID];
__device__ float g_qattn[9*BQ*25];
__device__ float g_bufA[3*NENT*BQ];
__device__ float g_bufB[3*NENT*BQ];
__device__ float g_sumsA[96];
__device__ float g_sumsB[96];

// CSR over targets (fwd+rev entries)
__device__ int  g_cnt[NENT];
__device__ int  g_offs[NENT+1];
__device__ int  g_fill[NENT];
__device__ int  g_bsum[64];
__device__ int  g_wind[NCSR];               // immutable weight-index per entry
__device__ __align__(8) int2 g_csr[NCSR];   // .x = src | (rei<<17), .y = weight bits (refreshed each call)

// B operands (bf16 hi only): [dir(2)][p 512 (perm gate col)][k 128]
__device__ __align__(16) __nv_bfloat16 g_Bmma[2*512*128];

// HW tanh (sm_75+): single MUFU op; sigmoid via identity
__device__ __forceinline__ float htanh(float x){
    float y; asm("tanh.approx.f32 %0, %1;" : "=f"(y) : "f"(x)); return y;
}
__device__ __forceinline__ float hsigm(float x){
    return fmaf(htanh(0.5f*x), 0.5f, 0.5f);
}

__device__ __forceinline__ uint32_t smem_u32(const void* p){
    uint32_t a;
    asm("{ .reg .u64 t; cvta.to.shared.u64 t, %1; cvt.u32.u64 %0, t; }" : "=r"(a) : "l"(p));
    return a;
}

#define LDSM4(r, addr) \
    asm volatile("ldmatrix.sync.aligned.m8n8.x4.shared.b16 {%0,%1,%2,%3}, [%4];" \
        : "=r"((r)[0]),"=r"((r)[1]),"=r"((r)[2]),"=r"((r)[3]) : "r"(addr))

#define MMA16816(d, a, b0, b1) \
    asm volatile("mma.sync.aligned.m16n8k16.row.col.f32.bf16.bf16.f32 " \
        "{%0,%1,%2,%3}, {%4,%5,%6,%7}, {%8,%9}, {%0,%1,%2,%3};" \
        : "+f"((d)[0]),"+f"((d)[1]),"+f"((d)[2]),"+f"((d)[3]) \
        : "r"((a)[0]),"r"((a)[1]),"r"((a)[2]),"r"((a)[3]), "r"(b0),"r"(b1))

#define CPA16(dst, src) asm volatile("cp.async.cg.shared.global [%0], [%1], 16;" :: "r"(dst), "l"(src))
#define CPA_COMMIT()    asm volatile("cp.async.commit_group;" ::: "memory")
#define CPA_WAIT0()     asm volatile("cp.async.wait_group 0;" ::: "memory")

#define SM_A   131072
#define DSMEM  196608

// ---------------- preprocessing ----------------
#define S2 25600
#define S4 393216
#define S5 98304
#define S6 131072
#define PREP_TOT (S2+S4+S5+S6)

__global__ void prep_kernel(const float* __restrict__ eWih, const float* __restrict__ eWhh,
                            const float* __restrict__ ebih, const float* __restrict__ ebhh,
                            const float* __restrict__ eemb,
                            const float* __restrict__ qWih, const float* __restrict__ qWhh,
                            const float* __restrict__ qbih, const float* __restrict__ qbhh,
                            const float* __restrict__ qemb, const int* __restrict__ queries){
    int idx = blockIdx.x*blockDim.x + threadIdx.x;
    if (idx < S2){
        int dir = idx / 12800; int rem = idx % 12800; int v = rem >> 9; int p = rem & 511;
        int j = ((p&3)<<7) + (p>>2);
        float acc = ebih[(dir<<9)+j] + ebhh[(dir<<9)+j];
        const float* wr = eWih + (dir<<16) + (j<<7);
        const float* er = eemb + (v<<7);
        for (int k=0;k<128;k++) acc += er[k]*wr[k];
        g_Ppre[(dir*12800) + (v<<9) + p] = acc;
        return;
    }
    idx -= S2;
    if (idx < S4){
        int pr = idx >> 16; int rem = idx & 65535; int p = rem >> 7; int k = rem & 127;
        int j = ((p&3)<<7) + (p>>2);
        g_Wqperm[idx] = qWhh[(pr<<16) + (j<<7) + k];
        return;
    }
    idx -= S4;
    if (idx < S5){
        int pr = idx >> 14; int rem = idx & 16383; int b = rem >> 9; int p = rem & 511;
        int j = ((p&3)<<7) + (p>>2);
        float acc = qbih[(pr<<9)+j] + qbhh[(pr<<9)+j];
        const float* wr = qWih + (pr<<16) + (j<<7);
        const float* xr = qemb + (queries[b]<<7);
        for (int k=0;k<128;k++) acc += xr[k]*wr[k];
        g_Pq[(pr<<14) + (b<<9) + p] = acc;
        return;
    }
    idx -= S5;
    if (idx < S6){
        int dir = idx >> 16;
        int p = (idx >> 7) & 511;
        int k = idx & 127;
        int q = p & 15, b = p >> 4;
        int u = 4*b + ((q&7)>>1);
        int gate = (q<8) ? (q&1) : 2+(q&1);
        int j = (gate<<7) + u;
        g_Bmma[idx] = __float2bfloat16(eWhh[(dir<<16) + (j<<7) + k]);
    }
}

// ---------------- CSR build ----------------
__global__ void zero_cnt(){
    int i = blockIdx.x*blockDim.x + threadIdx.x;
    if (i < NENT) g_cnt[i] = 0;
}
__global__ void count_k(const int* __restrict__ th, const int* __restrict__ tt){
    int e = blockIdx.x*blockDim.x + threadIdx.x;
    if (e >= NEDGE) return;
    atomicAdd(&g_cnt[tt[e]], 1);
    atomicAdd(&g_cnt[th[e]], 1);
}
__global__ void scan1(){
    __shared__ int sh[1024];
    int i = blockIdx.x*1024 + threadIdx.x;
    int v = (i<NENT)? g_cnt[i] : 0;
    sh[threadIdx.x]=v;
    __syncthreads();
    for (int off=1; off<1024; off<<=1){
        int t = (threadIdx.x>=off)? sh[threadIdx.x-off] : 0;
        __syncthreads();
        sh[threadIdx.x]+=t;
        __syncthreads();
    }
    if (i<NENT) g_offs[i] = sh[threadIdx.x]-v;
    if (threadIdx.x==1023) g_bsum[blockIdx.x]=sh[1023];
}
__global__ void scan2(){
    __shared__ int sh[64];
    int v = (threadIdx.x<NB_SCAN)? g_bsum[threadIdx.x] : 0;
    sh[threadIdx.x]=v;
    __syncthreads();
    for (int off=1; off<64; off<<=1){
        int t = (threadIdx.x>=off)? sh[threadIdx.x-off] : 0;
        __syncthreads();
        sh[threadIdx.x]+=t;
        __syncthreads();
    }
    if (threadIdx.x<NB_SCAN) g_bsum[threadIdx.x] = sh[threadIdx.x]-v;
    if (threadIdx.x==NB_SCAN-1) g_bsum[63] = sh[NB_SCAN-1];
}
__global__ void scan3(){
    int i = blockIdx.x*blockDim.x + threadIdx.x;
    if (i<NENT){
        int v = g_offs[i] + g_bsum[i>>10];
        g_offs[i]=v;
        g_fill[i]=v;
    }
    if (i==0) g_offs[NENT] = g_bsum[63];
}
__global__ void scatter_k(const int* __restrict__ rl, const int* __restrict__ th,
                          const int* __restrict__ tt){
    int e = blockIdx.x*blockDim.x + threadIdx.x;
    if (e >= NEDGE) return;
    int h = th[e], t2 = tt[e], r = rl[e];
    int wind = h*24 + r;
    int p1 = atomicAdd(&g_fill[t2], 1);
    g_csr[p1].x = h | (r<<17);
    g_wind[p1] = wind;
    int p2 = atomicAdd(&g_fill[h], 1);
    g_csr[p2].x = t2 | ((r+12)<<17);
    g_wind[p2] = wind;
}
__global__ void fill_w(){
    int i = blockIdx.x*blockDim.x + threadIdx.x;
    if (i >= NCSR) return;
    g_csr[i].y = __float_as_int(g_eattn[g_wind[i]]);
}

// ---------------- fused entity BiLSTM (R9 two-pass inner loop) ----------------
__global__ __launch_bounds__(512) void ent_fused(const int* __restrict__ degs){
    extern __shared__ __align__(16) char sm[];
    uint32_t sb = smem_u32(sm);
    int tid = threadIdx.x, lane = tid&31, wid = tid>>5;
    int warpM = wid&3, warpN = (wid>>2)&3;
    int mt = blockIdx.x, dir = blockIdx.y;
    int mbase = mt*128;

    #pragma unroll
    for (int j=0;j<16;j++){
        int i = tid + (j<<9);
        int p = i>>4, c = i&15;
        uint32_t dst = sb + ((p>>7)<<15) + ((p&127)<<8) + (((c ^ (p&7)))<<4);
        const void* src = g_Bmma + ((size_t)(dir<<9) + p)*128 + c*8;
        CPA16(dst, src);
    }
    CPA_COMMIT();

    int tg = lane>>2, tc = lane&3;
    int rows[4];
    #pragma unroll
    for (int mi=0;mi<2;mi++)
        #pragma unroll
        for (int rh=0;rh<2;rh++)
            rows[mi*2+rh] = warpM*32 + mi*16 + rh*8 + tg;

    float c_reg[4][8];
    uint32_t hp[4][8];
    const float* Pdir = g_Ppre + dir*12800;
    float* gH = dir ? g_hB : g_hF;

    {
        int t0 = dir ? 7 : 0;
        #pragma unroll
        for (int r4=0;r4<4;r4++){
            int row = rows[r4];
            int m = mbase + row;
            bool mv = (m < NENT);
            int d = mv ? degs[(m<<3)+t0] : 0;
            const float4* Pb = (const float4*)(Pdir + (d<<9));
            #pragma unroll
            for (int ch=0;ch<4;ch++){
                #pragma unroll
                for (int nt2=0;nt2<2;nt2++){
                    int u = ch*32 + warpN*8 + nt2*4 + tc;
                    float4 P = Pb[u];
                    float cn = hsigm(P.x)*htanh(P.z);
                    float h  = hsigm(P.w)*htanh(cn);
                    c_reg[ch][r4*2+nt2] = cn;
                    __nv_bfloat16 hh = __float2bfloat16(h);
                    __nv_bfloat16 hl = __float2bfloat16(h - __bfloat162float(hh));
                    uint32_t off = (row<<8) + ((((u>>3) ^ (row&7)))<<4) + ((u&7)<<1);
                    *(__nv_bfloat16*)(sm + SM_A + off) = hh;
                    *(__nv_bfloat16*)(sm + SM_A + 32768 + off) = hl;
                }
            }
        }
    }
    CPA_WAIT0();
    __syncthreads();

    int aRowBase = warpM*32 + (lane&7) + ((lane>>3)&1)*8;
    int aHi = lane>>4;
    int bRowBase = warpN*32 + (lane&7) + (lane>>4)*8;
    int bHi = (lane>>3)&1;

    #pragma unroll 1
    for (int s=1;s<8;s++){
        int t = dir ? 7-s : s;
        #pragma unroll
        for (int ch=0;ch<4;ch++){
            float acc[2][4][4];
            #pragma unroll
            for (int a1=0;a1<2;a1++)
                #pragma unroll
                for (int a2=0;a2<4;a2++)
                    #pragma unroll
                    for (int a3=0;a3<4;a3++) acc[a1][a2][a3]=0.f;

            #pragma unroll
            for (int pass=0;pass<2;pass++){
                uint32_t aP = sb + SM_A + (pass<<15);
                uint32_t bP = sb + (ch<<15);
                #pragma unroll
                for (int kc=0;kc<8;kc++){
                    uint32_t afr[2][4], bfr[2][4];
                    #pragma unroll
                    for (int mi=0;mi<2;mi++){
                        int r = aRowBase + mi*16;
                        LDSM4(afr[mi], aP + (r<<8) + (((2*kc + aHi) ^ (r&7))<<4));
                    }
                    #pragma unroll
                    for (int nt2=0;nt2<2;nt2++){
                        int r = bRowBase + nt2*16;
                        LDSM4(bfr[nt2], bP + (r<<8) + (((2*kc + bHi) ^ (r&7))<<4));
                    }
                    #pragma unroll
                    for (int mi=0;mi<2;mi++)
                        #pragma unroll
                        for (int nt2=0;nt2<2;nt2++){
                            MMA16816(acc[mi][2*nt2],   afr[mi], bfr[nt2][0], bfr[nt2][1]);
                            MMA16816(acc[mi][2*nt2+1], afr[mi], bfr[nt2][2], bfr[nt2][3]);
                        }
                }
            }
            #pragma unroll
            for (int mi=0;mi<2;mi++){
                #pragma unroll
                for (int rh=0;rh<2;rh++){
                    int r4 = mi*2+rh;
                    int row = rows[r4];
                    int m = mbase + row;
                    bool mv = (m < NENT);
                    int d = mv ? degs[(m<<3)+t] : 0;
                    const float4* Pb = (const float4*)(Pdir + (d<<9));
                    #pragma unroll
                    for (int nt2=0;nt2<2;nt2++){
                        int u = ch*32 + warpN*8 + nt2*4 + tc;
                        float4 P = Pb[u];
                        float ig = hsigm(acc[mi][2*nt2  ][rh*2+0] + P.x);
                        float fg = hsigm(acc[mi][2*nt2  ][rh*2+1] + P.y);
                        float gg = htanh(acc[mi][2*nt2+1][rh*2+0] + P.z);
                        float og = hsigm(acc[mi][2*nt2+1][rh*2+1] + P.w);
                        float cn = fg*c_reg[ch][r4*2+nt2] + ig*gg;
                        c_reg[ch][r4*2+nt2] = cn;
                        float h = og*htanh(cn);
                        if (s==7){
                            if (mv) gH[(m<<7)+u] = h;
                        } else {
                            __nv_bfloat16 hh = __float2bfloat16(h);
                            __nv_bfloat16 hl = __float2bfloat16(h - __bfloat162float(hh));
                            hp[ch][r4*2+nt2] = (uint32_t)__bfloat16_as_ushort(hh)
                                             | ((uint32_t)__bfloat16_as_ushort(hl)<<16);
                        }
                    }
                }
            }
        }
        if (s<7){
            __syncthreads();
            #pragma unroll
            for (int ch=0;ch<4;ch++){
                #pragma unroll
                for (int r4=0;r4<4;r4++){
                    int row = rows[r4];
                    #pragma unroll
                    for (int nt2=0;nt2<2;nt2++){
                        int u = ch*32 + warpN*8 + nt2*4 + tc;
                        uint32_t v = hp[ch][r4*2+nt2];
                        uint32_t off = (row<<8) + ((((u>>3) ^ (row&7)))<<4) + ((u&7)<<1);
                        *(uint16_t*)(sm + SM_A + off) = (uint16_t)(v & 0xffffu);
                        *(uint16_t*)(sm + SM_A + 32768 + off) = (uint16_t)(v >> 16);
                    }
                }
            }
            __syncthreads();
        }
    }
}

// ---------------- entity attention ----------------
__global__ void ent_attn_kernel(const float* __restrict__ W, const float* __restrict__ bias){
    __shared__ float Ws[8192];
    int tid = threadIdx.x;
    for (int i=tid;i<8192;i+=256) Ws[i]=0.f;
    __syncthreads();
    for (int i=tid;i<24*256;i+=256){ int o=i>>8, k=i&255; Ws[(k<<5)+o]=W[i]; }
    __syncthreads();
    int lane = tid&31;
    int wid = (blockIdx.x<<3) + (tid>>5);
    int nw  = gridDim.x<<3;
    float bv = (lane<24)? bias[lane] : -1e30f;
    for (int n=wid; n<NENT; n+=nw){
        float acc = bv;
        const float* hf = g_hF + (n<<7);
        const float* hb = g_hB + (n<<7);
        for (int k=0;k<128;k++) acc += hf[k]*Ws[(k<<5)+lane];
        for (int k=0;k<128;k++) acc += hb[k]*Ws[((k+128)<<5)+lane];
        float mx = acc;
        for (int o=16;o;o>>=1) mx = fmaxf(mx, __shfl_xor_sync(0xffffffffu, mx, o));
        float e = (lane<24)? expf(acc-mx) : 0.f;
        float s = e;
        for (int o=16;o;o>>=1) s += __shfl_xor_sync(0xffffffffu, s, o);
        if (lane<24) g_eattn[n*24+lane] = e/s;
    }
}

// ---------------- query LSTMs ----------------
__global__ void q_step0(){
    int idx = blockIdx.x*blockDim.x + threadIdx.x;
    if (idx >= 6*BQ*HID) return;
    int pr = idx/4096; int rem = idx&4095; int b = rem>>7; int u = rem&127;
    float4 P = *(const float4*)(g_Pq + (pr<<14) + (b<<9) + (u<<2));
    float cn = hsigm(P.x)*htanh(P.z);
    g_qc[idx] = cn;
    g_qh[pr*3*4096 + rem] = hsigm(P.w)*htanh(cn);
}

__global__ __launch_bounds__(256) void q_step(int s){
    int pr = blockIdx.y;
    int cb = blockIdx.x<<6;
    const float* h_in = g_qh + (pr*3 + s-1)*4096;
    float* h_out      = g_qh + (pr*3 + s)*4096;
    __shared__ float As[16][36];
    __shared__ float Bs[16][68];
    int tid=threadIdx.x;
    int ty=tid>>4, tx=tid&15;
    const float* Wp = g_Wqperm + (pr<<16);
    float acc[2][4] = {};
    int lrA = tid>>3; int kqA = (tid&7)<<1;
    int lrB = tid>>2; int kqB = (tid&3)<<2;
    for (int kb=0;kb<128;kb+=16){
        float2 a2 = *(const float2*)(h_in + (lrA<<7) + kb + kqA);
        float4 b4 = *(const float4*)(Wp + ((cb+lrB)<<7) + kb + kqB);
        As[kqA+0][lrA]=a2.x; As[kqA+1][lrA]=a2.y;
        Bs[kqB+0][lrB]=b4.x; Bs[kqB+1][lrB]=b4.y; Bs[kqB+2][lrB]=b4.z; Bs[kqB+3][lrB]=b4.w;
        __syncthreads();
        #pragma unroll
        for (int k=0;k<16;k++){
            float a0=As[k][(ty<<1)], a1=As[k][(ty<<1)+1];
            float4 b=*(const float4*)&Bs[k][tx<<2];
            acc[0][0]+=a0*b.x; acc[0][1]+=a0*b.y; acc[0][2]+=a0*b.z; acc[0][3]+=a0*b.w;
            acc[1][0]+=a1*b.x; acc[1][1]+=a1*b.y; acc[1][2]+=a1*b.z; acc[1][3]+=a1*b.w;
        }
        __syncthreads();
    }
    int u = (cb>>2)+tx;
    #pragma unroll
    for (int i=0;i<2;i++){
        int b = (ty<<1)+i;
        float4 P = *(const float4*)(g_Pq + (pr<<14) + (b<<9) + cb + (tx<<2));
        float ig=hsigm(acc[i][0]+P.x), fg=hsigm(acc[i][1]+P.y);
        float gg=htanh(acc[i][2]+P.z), og=hsigm(acc[i][3]+P.w);
        int ci = pr*4096 + (b<<7) + u;
        float cn = fg*g_qc[ci] + ig*gg;
        g_qc[ci]=cn;
        h_out[(b<<7)+u]=og*htanh(cn);
    }
}

__global__ void q_attn_kernel(const float* __restrict__ W, const float* __restrict__ bias){
    __shared__ float Ws[8192];
    int tid=threadIdx.x;
    for (int i=tid;i<8192;i+=256) Ws[i]=0.f;
    __syncthreads();
    for (int i=tid;i<25*256;i+=256){ int o=i>>8,k=i&255; Ws[(k<<5)+o]=W[i]; }
    __syncthreads();
    int lane=tid&31;
    int gw=(blockIdx.x<<3)+(tid>>5);
    if (gw>=288) return;
    int b=gw&31, rt=gw>>5; int r=rt/3, t=rt%3;
    const float* hf = g_qh + ((r*2  )*3 + t    )*4096 + (b<<7);
    const float* hb = g_qh + ((r*2+1)*3 + (2-t))*4096 + (b<<7);
    float acc = (lane<25)? bias[lane] : -1e30f;
    for (int k=0;k<128;k++) acc += hf[k]*Ws[(k<<5)+lane];
    for (int k=0;k<128;k++) acc += hb[k]*Ws[((k+128)<<5)+lane];
    float mx=acc;
    for (int o=16;o;o>>=1) mx=fmaxf(mx,__shfl_xor_sync(0xffffffffu,mx,o));
    float e=(lane<25)?expf(acc-mx):0.f;
    float s=e;
    for (int o=16;o;o>>=1) s+=__shfl_xor_sync(0xffffffffu,s,o);
    if (lane<25) g_qattn[rt*800 + b*25 + lane] = e/s;
}

// ---------------- propagation (CSR gather + fused colsum) ----------------
__global__ void init_sums(){
    int i = threadIdx.x;
    if (i<96){ g_sumsA[i]=1.f; g_sumsB[i]=0.f; }
}

// ab=0: in=bufA/sumsA, out=bufB, colsum->sumsB ; ab=1: in=bufB/sumsB, out=bufA, colsum->sumsA
// t0flag: step-0 input is the one-hot memory (heads) — no buffer reads at all.
__global__ __launch_bounds__(256) void csr_step(int ab, int t, int t0flag,
                                                const int* __restrict__ heads){
    int r = blockIdx.y;
    __shared__ float qs[800];
    const float* qa = g_qattn + (r*3+t)*800;
    for (int i=threadIdx.x;i<800;i+=256) qs[i]=qa[i];
    __syncthreads();
    const float* inb  = (ab ? g_bufB : g_bufA) + r*NENT*BQ;
    float*       outb = (ab ? g_bufA : g_bufB) + r*NENT*BQ;
    const float* sums =  ab ? g_sumsB : g_sumsA;
    float*       osum =  ab ? g_sumsA : g_sumsB;
    int lane = threadIdx.x&31, wid = threadIdx.x>>5;
    float inv = __fdividef(1.f, fmaxf(1e-20f, sums[r*32+lane]));
    float qlast = qs[lane*25+24];
    int hb = t0flag ? heads[lane] : 0;
    float csum = 0.f;
    int n0 = (blockIdx.x<<6) + (wid<<3);
    #pragma unroll 1
    for (int j=0;j<8;j++){
        int n = n0+j;
        if (n < NENT){
            float acc;
            int s0 = g_offs[n], s1 = g_offs[n+1];
            if (t0flag){
                acc = qlast * ((hb==n)? 1.f : 0.f);
                for (int i=s0;i<s1;i++){
                    int2 en = g_csr[i];
                    float val = qs[lane*25 + (en.x>>17)] * __int_as_float(en.y);
                    acc += ((en.x & 0x1FFFF)==hb) ? val : 0.f;
                }
            } else {
                acc = qlast * inb[(n<<5)+lane];
                for (int i=s0;i<s1;i++){
                    int2 en = g_csr[i];
                    float val = qs[lane*25 + (en.x>>17)] * __int_as_float(en.y);
                    acc += val * inb[((en.x & 0x1FFFF)<<5) + lane];
                }
            }
            float v = acc*inv;
            outb[(n<<5)+lane] = v;
            csum += v;
        }
    }
    __shared__ float sh[8][32];
    sh[wid][lane]=csum;
    __syncthreads();
    if (wid==0){
        float s=0.f;
        #pragma unroll
        for (int i=0;i<8;i++) s+=sh[i][lane];
        atomicAdd(&osum[r*32+lane], s);
    }
}

__global__ void zero_sums(int sel){
    if (threadIdx.x < 96) (sel ? g_sumsB : g_sumsA)[threadIdx.x] = 0.f;
}

__global__ void trans_out(float* __restrict__ out){
    __shared__ float tile[32][33];
    __shared__ float invs[96];
    int tx=threadIdx.x, ty=threadIdx.y;
    if (ty<3) invs[ty*32+tx] = __fdividef(1.f, fmaxf(1e-20f, g_sumsB[ty*32+tx]));
    __syncthreads();
    int n0=blockIdx.x<<5;
    int n=n0+ty;
    float v = 0.f;
    if (n<NENT){
        int i = (n<<5)+tx;
        v = g_bufB[i]*invs[tx] + g_bufB[NENT*BQ+i]*invs[32+tx] + g_bufB[2*NENT*BQ+i]*invs[64+tx];
    }
    tile[ty][tx] = v;
    __syncthreads();
    int nn=n0+tx;
    if (nn<NENT) out[ty*NENT+nn] = tile[tx][ty];
}

// ---------------- host ----------------
extern "C" void kernel_launch(void* const* d_in, const int* in_sizes, int n_in,
                              void* d_out, int out_size){
    const int*   queries=(const int*)d_in[0];
    const int*   heads  =(const int*)d_in[1];
    const int*   rels   =(const int*)d_in[2];
    const int*   t_heads=(const int*)d_in[3];
    const int*   t_tails=(const int*)d_in[4];
    const int*   degs   =(const int*)d_in[5];
    const float* qemb=(const float*)d_in[6];
    const float* eemb=(const float*)d_in[7];
    const float* qWih=(const float*)d_in[8];
    const float* qWhh=(const float*)d_in[9];
    const float* qbih=(const float*)d_in[10];
    const float* qbhh=(const float*)d_in[11];
    const float* eWih=(const float*)d_in[12];
    const float* eWhh=(const float*)d_in[13];
    const float* ebih=(const float*)d_in[14];
    const float* ebhh=(const float*)d_in[15];
    const float* qlW=(const float*)d_in[16];
    const float* qlb=(const float*)d_in[17];
    const float* elW=(const float*)d_in[18];
    const float* elb=(const float*)d_in[19];
    float* out=(float*)d_out;

    cudaFuncSetAttribute(ent_fused, cudaFuncAttributeMaxDynamicSharedMemorySize, DSMEM);

    prep_kernel<<<(PREP_TOT+255)/256,256>>>(eWih,eWhh,ebih,ebhh,eemb,
                                            qWih,qWhh,qbih,qbhh,qemb,queries);
    // CSR build (rebuilt every call; deterministic given inputs)
    zero_cnt<<<(NENT+255)/256,256>>>();
    count_k<<<(NEDGE+255)/256,256>>>(t_heads, t_tails);
    scan1<<<NB_SCAN,1024>>>();
    scan2<<<1,64>>>();
    scan3<<<(NENT+255)/256,256>>>();
    scatter_k<<<(NEDGE+255)/256,256>>>(rels, t_heads, t_tails);

    // entity BiLSTM: all 8 steps, both directions, one launch
    ent_fused<<<dim3(MTILES,2),512,DSMEM>>>(degs);

    ent_attn_kernel<<<1024,256>>>(elW, elb);
    fill_w<<<(NCSR+255)/256,256>>>();

    // query BiLSTMs
    q_step0<<<96,256>>>();
    q_step<<<dim3(8,6),256>>>(1);
    q_step<<<dim3(8,6),256>>>(2);
    q_attn_kernel<<<36,256>>>(qlW, qlb);

    // propagation: 3 ranks per launch; colsum fused; t=0 one-hot (no buffer init)
    init_sums<<<1,128>>>();
    csr_step<<<dim3(782,3),256>>>(0, 0, 1, heads);   // one-hot -> bufB, colsum -> sumsB
    zero_sums<<<1,128>>>(0);
    csr_step<<<dim3(782,3),256>>>(1, 1, 0, heads);   // bufB -> bufA, colsum -> sumsA
    zero_sums<<<1,128>>>(1);
    csr_step<<<dim3(782,3),256>>>(0, 2, 0, heads);   // bufA -> bufB, colsum -> sumsB
    trans_out<<<1563,dim3(32,32)>>>(out);
}

// round 12
// speedup vs baseline: 1.8810x; 1.2817x over previous
#include <cuda_runtime.h>
#include <cuda_bf16.h>
#include <math.h>
#include <stdint.h>

#define NENT 50000
#define MTILES 391
#define NEDGE 400000
#define NCSR  (2*NEDGE)
#define BQ 32
#define HID 128
#define G4 512
#define NB_SCAN 49

// ---------------- scratch (device globals; no allocation) ----------------
__device__ __align__(16) float g_Ppre[2*25*G4];
__device__ __align__(16) float g_hF[NENT*HID];
__device__ __align__(16) float g_hB[NENT*HID];
__device__ float g_eattn[NENT*24];
__device__ __align__(16) float g_Wqperm[6*G4*HID];
__device__ __align__(16) float g_Pq[6*BQ*G4];
__device__ __align__(16) float g_qh[18*BQ*HID];
__device__ float g_qc[6*BQ*HID];
__device__ float g_qattn[9*BQ*25];
__device__ float g_bufA[3*NENT*BQ];
__device__ float g_bufB[3*NENT*BQ];
__device__ float g_sumsA[96];
__device__ float g_sumsB[96];

// CSR over targets (fwd+rev entries)
__device__ int  g_cnt[NENT];
__device__ int  g_offs[NENT+1];
__device__ int  g_fill[NENT];
__device__ int  g_bsum[64];
__device__ int  g_wind[NCSR];
__device__ __align__(8) int2 g_csr[NCSR];

// B operands (bf16 hi only): [dir(2)][p 512 (perm gate col)][k 128]
__device__ __align__(16) __nv_bfloat16 g_Bmma[2*512*128];

// HW tanh (sm_75+): single MUFU op; sigmoid via identity
__device__ __forceinline__ float htanh(float x){
    float y; asm("tanh.approx.f32 %0, %1;" : "=f"(y) : "f"(x)); return y;
}
__device__ __forceinline__ float hsigm(float x){
    return fmaf(htanh(0.5f*x), 0.5f, 0.5f);
}

__device__ __forceinline__ uint32_t smem_u32(const void* p){
    uint32_t a;
    asm("{ .reg .u64 t; cvta.to.shared.u64 t, %1; cvt.u32.u64 %0, t; }" : "=r"(a) : "l"(p));
    return a;
}

#define LDSM4(r, addr) \
    asm volatile("ldmatrix.sync.aligned.m8n8.x4.shared.b16 {%0,%1,%2,%3}, [%4];" \
        : "=r"((r)[0]),"=r"((r)[1]),"=r"((r)[2]),"=r"((r)[3]) : "r"(addr))

#define MMA16816(d, a, b0, b1) \
    asm volatile("mma.sync.aligned.m16n8k16.row.col.f32.bf16.bf16.f32 " \
        "{%0,%1,%2,%3}, {%4,%5,%6,%7}, {%8,%9}, {%0,%1,%2,%3};" \
        : "+f"((d)[0]),"+f"((d)[1]),"+f"((d)[2]),"+f"((d)[3]) \
        : "r"((a)[0]),"r"((a)[1]),"r"((a)[2]),"r"((a)[3]), "r"(b0),"r"(b1))

#define CPA16(dst, src) asm volatile("cp.async.cg.shared.global [%0], [%1], 16;" :: "r"(dst), "l"(src))
#define CPA_COMMIT()    asm volatile("cp.async.commit_group;" ::: "memory")
#define CPA_WAIT0()     asm volatile("cp.async.wait_group 0;" ::: "memory")

#define SM_A   131072
#define DSMEM  163840

// ---------------- preprocessing ----------------
#define S2 25600
#define S4 393216
#define S5 98304
#define S6 131072
#define PREP_TOT (S2+S4+S5+S6)

__global__ void prep_kernel(const float* __restrict__ eWih, const float* __restrict__ eWhh,
                            const float* __restrict__ ebih, const float* __restrict__ ebhh,
                            const float* __restrict__ eemb,
                            const float* __restrict__ qWih, const float* __restrict__ qWhh,
                            const float* __restrict__ qbih, const float* __restrict__ qbhh,
                            const float* __restrict__ qemb, const int* __restrict__ queries){
    int idx = blockIdx.x*blockDim.x + threadIdx.x;
    if (idx < S2){
        int dir = idx / 12800; int rem = idx % 12800; int v = rem >> 9; int p = rem & 511;
        int j = ((p&3)<<7) + (p>>2);
        float acc = ebih[(dir<<9)+j] + ebhh[(dir<<9)+j];
        const float* wr = eWih + (dir<<16) + (j<<7);
        const float* er = eemb + (v<<7);
        for (int k=0;k<128;k++) acc += er[k]*wr[k];
        g_Ppre[(dir*12800) + (v<<9) + p] = acc;
        return;
    }
    idx -= S2;
    if (idx < S4){
        int pr = idx >> 16; int rem = idx & 65535; int p = rem >> 7; int k = rem & 127;
        int j = ((p&3)<<7) + (p>>2);
        g_Wqperm[idx] = qWhh[(pr<<16) + (j<<7) + k];
        return;
    }
    idx -= S4;
    if (idx < S5){
        int pr = idx >> 14; int rem = idx & 16383; int b = rem >> 9; int p = rem & 511;
        int j = ((p&3)<<7) + (p>>2);
        float acc = qbih[(pr<<9)+j] + qbhh[(pr<<9)+j];
        const float* wr = qWih + (pr<<16) + (j<<7);
        const float* xr = qemb + (queries[b]<<7);
        for (int k=0;k<128;k++) acc += xr[k]*wr[k];
        g_Pq[(pr<<14) + (b<<9) + p] = acc;
        return;
    }
    idx -= S5;
    if (idx < S6){
        int dir = idx >> 16;
        int p = (idx >> 7) & 511;
        int k = idx & 127;
        int q = p & 15, b = p >> 4;
        int u = 4*b + ((q&7)>>1);
        int gate = (q<8) ? (q&1) : 2+(q&1);
        int j = (gate<<7) + u;
        g_Bmma[idx] = __float2bfloat16(eWhh[(dir<<16) + (j<<7) + k]);
    }
}

// ---------------- CSR build ----------------
__global__ void zero_cnt(){
    int i = blockIdx.x*blockDim.x + threadIdx.x;
    if (i < NENT) g_cnt[i] = 0;
}
__global__ void count_k(const int* __restrict__ th, const int* __restrict__ tt){
    int e = blockIdx.x*blockDim.x + threadIdx.x;
    if (e >= NEDGE) return;
    atomicAdd(&g_cnt[tt[e]], 1);
    atomicAdd(&g_cnt[th[e]], 1);
}
__global__ void scan1(){
    __shared__ int sh[1024];
    int i = blockIdx.x*1024 + threadIdx.x;
    int v = (i<NENT)? g_cnt[i] : 0;
    sh[threadIdx.x]=v;
    __syncthreads();
    for (int off=1; off<1024; off<<=1){
        int t = (threadIdx.x>=off)? sh[threadIdx.x-off] : 0;
        __syncthreads();
        sh[threadIdx.x]+=t;
        __syncthreads();
    }
    if (i<NENT) g_offs[i] = sh[threadIdx.x]-v;
    if (threadIdx.x==1023) g_bsum[blockIdx.x]=sh[1023];
}
__global__ void scan2(){
    __shared__ int sh[64];
    int v = (threadIdx.x<NB_SCAN)? g_bsum[threadIdx.x] : 0;
    sh[threadIdx.x]=v;
    __syncthreads();
    for (int off=1; off<64; off<<=1){
        int t = (threadIdx.x>=off)? sh[threadIdx.x-off] : 0;
        __syncthreads();
        sh[threadIdx.x]+=t;
        __syncthreads();
    }
    if (threadIdx.x<NB_SCAN) g_bsum[threadIdx.x] = sh[threadIdx.x]-v;
    if (threadIdx.x==NB_SCAN-1) g_bsum[63] = sh[NB_SCAN-1];
}
__global__ void scan3(){
    int i = blockIdx.x*blockDim.x + threadIdx.x;
    if (i<NENT){
        int v = g_offs[i] + g_bsum[i>>10];
        g_offs[i]=v;
        g_fill[i]=v;
    }
    if (i==0) g_offs[NENT] = g_bsum[63];
}
__global__ void scatter_k(const int* __restrict__ rl, const int* __restrict__ th,
                          const int* __restrict__ tt){
    int e = blockIdx.x*blockDim.x + threadIdx.x;
    if (e >= NEDGE) return;
    int h = th[e], t2 = tt[e], r = rl[e];
    int wind = h*24 + r;
    int p1 = atomicAdd(&g_fill[t2], 1);
    g_csr[p1].x = h | (r<<17);
    g_wind[p1] = wind;
    int p2 = atomicAdd(&g_fill[h], 1);
    g_csr[p2].x = t2 | ((r+12)<<17);
    g_wind[p2] = wind;
}
__global__ void fill_w(){
    int i = blockIdx.x*blockDim.x + threadIdx.x;
    if (i >= NCSR) return;
    g_csr[i].y = __float_as_int(g_eattn[g_wind[i]]);
}

// ---------------- fused entity BiLSTM (single bf16 A plane) ----------------
__global__ __launch_bounds__(512) void ent_fused(const int* __restrict__ degs){
    extern __shared__ __align__(16) char sm[];
    uint32_t sb = smem_u32(sm);
    int tid = threadIdx.x, lane = tid&31, wid = tid>>5;
    int warpM = wid&3, warpN = (wid>>2)&3;
    int mt = blockIdx.x, dir = blockIdx.y;
    int mbase = mt*128;

    #pragma unroll
    for (int j=0;j<16;j++){
        int i = tid + (j<<9);
        int p = i>>4, c = i&15;
        uint32_t dst = sb + ((p>>7)<<15) + ((p&127)<<8) + (((c ^ (p&7)))<<4);
        const void* src = g_Bmma + ((size_t)(dir<<9) + p)*128 + c*8;
        CPA16(dst, src);
    }
    CPA_COMMIT();

    int tg = lane>>2, tc = lane&3;
    int rows[4];
    #pragma unroll
    for (int mi=0;mi<2;mi++)
        #pragma unroll
        for (int rh=0;rh<2;rh++)
            rows[mi*2+rh] = warpM*32 + mi*16 + rh*8 + tg;

    float c_reg[4][8];
    uint16_t hp[4][8];
    const float* Pdir = g_Ppre + dir*12800;
    float* gH = dir ? g_hB : g_hF;

    {
        int t0 = dir ? 7 : 0;
        #pragma unroll
        for (int r4=0;r4<4;r4++){
            int row = rows[r4];
            int m = mbase + row;
            bool mv = (m < NENT);
            int d = mv ? degs[(m<<3)+t0] : 0;
            const float4* Pb = (const float4*)(Pdir + (d<<9));
            #pragma unroll
            for (int ch=0;ch<4;ch++){
                #pragma unroll
                for (int nt2=0;nt2<2;nt2++){
                    int u = ch*32 + warpN*8 + nt2*4 + tc;
                    float4 P = Pb[u];
                    float cn = hsigm(P.x)*htanh(P.z);
                    float h  = hsigm(P.w)*htanh(cn);
                    c_reg[ch][r4*2+nt2] = cn;
                    uint32_t off = (row<<8) + ((((u>>3) ^ (row&7)))<<4) + ((u&7)<<1);
                    *(__nv_bfloat16*)(sm + SM_A + off) = __float2bfloat16(h);
                }
            }
        }
    }
    CPA_WAIT0();
    __syncthreads();

    int aRowBase = warpM*32 + (lane&7) + ((lane>>3)&1)*8;
    int aHi = lane>>4;
    int bRowBase = warpN*32 + (lane&7) + (lane>>4)*8;
    int bHi = (lane>>3)&1;

    #pragma unroll 1
    for (int s=1;s<8;s++){
        int t = dir ? 7-s : s;
        #pragma unroll
        for (int ch=0;ch<4;ch++){
            float acc[2][4][4];
            #pragma unroll
            for (int a1=0;a1<2;a1++)
                #pragma unroll
                for (int a2=0;a2<4;a2++)
                    #pragma unroll
                    for (int a3=0;a3<4;a3++) acc[a1][a2][a3]=0.f;

            uint32_t aP = sb + SM_A;
            uint32_t bP = sb + (ch<<15);
            #pragma unroll
            for (int kc=0;kc<8;kc++){
                uint32_t afr[2][4], bfr[2][4];
                #pragma unroll
                for (int mi=0;mi<2;mi++){
                    int r = aRowBase + mi*16;
                    LDSM4(afr[mi], aP + (r<<8) + (((2*kc + aHi) ^ (r&7))<<4));
                }
                #pragma unroll
                for (int nt2=0;nt2<2;nt2++){
                    int r = bRowBase + nt2*16;
                    LDSM4(bfr[nt2], bP + (r<<8) + (((2*kc + bHi) ^ (r&7))<<4));
                }
                #pragma unroll
                for (int mi=0;mi<2;mi++)
                    #pragma unroll
                    for (int nt2=0;nt2<2;nt2++){
                        MMA16816(acc[mi][2*nt2],   afr[mi], bfr[nt2][0], bfr[nt2][1]);
                        MMA16816(acc[mi][2*nt2+1], afr[mi], bfr[nt2][2], bfr[nt2][3]);
                    }
            }
            #pragma unroll
            for (int mi=0;mi<2;mi++){
                #pragma unroll
                for (int rh=0;rh<2;rh++){
                    int r4 = mi*2+rh;
                    int row = rows[r4];
                    int m = mbase + row;
                    bool mv = (m < NENT);
                    int d = mv ? degs[(m<<3)+t] : 0;
                    const float4* Pb = (const float4*)(Pdir + (d<<9));
                    #pragma unroll
                    for (int nt2=0;nt2<2;nt2++){
                        int u = ch*32 + warpN*8 + nt2*4 + tc;
                        float4 P = Pb[u];
                        float ig = hsigm(acc[mi][2*nt2  ][rh*2+0] + P.x);
                        float fg = hsigm(acc[mi][2*nt2  ][rh*2+1] + P.y);
                        float gg = htanh(acc[mi][2*nt2+1][rh*2+0] + P.z);
                        float og = hsigm(acc[mi][2*nt2+1][rh*2+1] + P.w);
                        float cn = fg*c_reg[ch][r4*2+nt2] + ig*gg;
                        c_reg[ch][r4*2+nt2] = cn;
                        float h = og*htanh(cn);
                        if (s==7){
                            if (mv) gH[(m<<7)+u] = h;
                        } else {
                            hp[ch][r4*2+nt2] = __bfloat16_as_ushort(__float2bfloat16(h));
                        }
                    }
                }
            }
        }
        if (s<7){
            __syncthreads();
            #pragma unroll
            for (int ch=0;ch<4;ch++){
                #pragma unroll
                for (int r4=0;r4<4;r4++){
                    int row = rows[r4];
                    #pragma unroll
                    for (int nt2=0;nt2<2;nt2++){
                        int u = ch*32 + warpN*8 + nt2*4 + tc;
                        uint32_t off = (row<<8) + ((((u>>3) ^ (row&7)))<<4) + ((u&7)<<1);
                        *(uint16_t*)(sm + SM_A + off) = hp[ch][r4*2+nt2];
                    }
                }
            }
            __syncthreads();
        }
    }
}

// ---------------- entity attention ----------------
__global__ void ent_attn_kernel(const float* __restrict__ W, const float* __restrict__ bias){
    __shared__ float Ws[8192];
    int tid = threadIdx.x;
    for (int i=tid;i<8192;i+=256) Ws[i]=0.f;
    __syncthreads();
    for (int i=tid;i<24*256;i+=256){ int o=i>>8, k=i&255; Ws[(k<<5)+o]=W[i]; }
    __syncthreads();
    int lane = tid&31;
    int wid = (blockIdx.x<<3) + (tid>>5);
    int nw  = gridDim.x<<3;
    float bv = (lane<24)? bias[lane] : -1e30f;
    for (int n=wid; n<NENT; n+=nw){
        float acc = bv;
        const float* hf = g_hF + (n<<7);
        const float* hb = g_hB + (n<<7);
        for (int k=0;k<128;k++) acc += hf[k]*Ws[(k<<5)+lane];
        for (int k=0;k<128;k++) acc += hb[k]*Ws[((k+128)<<5)+lane];
        float mx = acc;
        for (int o=16;o;o>>=1) mx = fmaxf(mx, __shfl_xor_sync(0xffffffffu, mx, o));
        float e = (lane<24)? expf(acc-mx) : 0.f;
        float s = e;
        for (int o=16;o;o>>=1) s += __shfl_xor_sync(0xffffffffu, s, o);
        if (lane<24) g_eattn[n*24+lane] = e/s;
    }
}

// ---------------- query LSTMs ----------------
__global__ void q_step0(){
    int idx = blockIdx.x*blockDim.x + threadIdx.x;
    if (idx >= 6*BQ*HID) return;
    int pr = idx/4096; int rem = idx&4095; int b = rem>>7; int u = rem&127;
    float4 P = *(const float4*)(g_Pq + (pr<<14) + (b<<9) + (u<<2));
    float cn = hsigm(P.x)*htanh(P.z);
    g_qc[idx] = cn;
    g_qh[pr*3*4096 + rem] = hsigm(P.w)*htanh(cn);
}

__global__ __launch_bounds__(256) void q_step(int s){
    int pr = blockIdx.y;
    int cb = blockIdx.x<<6;
    const float* h_in = g_qh + (pr*3 + s-1)*4096;
    float* h_out      = g_qh + (pr*3 + s)*4096;
    __shared__ float As[16][36];
    __shared__ float Bs[16][68];
    int tid=threadIdx.x;
    int ty=tid>>4, tx=tid&15;
    const float* Wp = g_Wqperm + (pr<<16);
    float acc[2][4] = {};
    int lrA = tid>>3; int kqA = (tid&7)<<1;
    int lrB = tid>>2; int kqB = (tid&3)<<2;
    for (int kb=0;kb<128;kb+=16){
        float2 a2 = *(const float2*)(h_in + (lrA<<7) + kb + kqA);
        float4 b4 = *(const float4*)(Wp + ((cb+lrB)<<7) + kb + kqB);
        As[kqA+0][lrA]=a2.x; As[kqA+1][lrA]=a2.y;
        Bs[kqB+0][lrB]=b4.x; Bs[kqB+1][lrB]=b4.y; Bs[kqB+2][lrB]=b4.z; Bs[kqB+3][lrB]=b4.w;
        __syncthreads();
        #pragma unroll
        for (int k=0;k<16;k++){
            float a0=As[k][(ty<<1)], a1=As[k][(ty<<1)+1];
            float4 b=*(const float4*)&Bs[k][tx<<2];
            acc[0][0]+=a0*b.x; acc[0][1]+=a0*b.y; acc[0][2]+=a0*b.z; acc[0][3]+=a0*b.w;
            acc[1][0]+=a1*b.x; acc[1][1]+=a1*b.y; acc[1][2]+=a1*b.z; acc[1][3]+=a1*b.w;
        }
        __syncthreads();
    }
    int u = (cb>>2)+tx;
    #pragma unroll
    for (int i=0;i<2;i++){
        int b = (ty<<1)+i;
        float4 P = *(const float4*)(g_Pq + (pr<<14) + (b<<9) + cb + (tx<<2));
        float ig=hsigm(acc[i][0]+P.x), fg=hsigm(acc[i][1]+P.y);
        float gg=htanh(acc[i][2]+P.z), og=hsigm(acc[i][3]+P.w);
        int ci = pr*4096 + (b<<7) + u;
        float cn = fg*g_qc[ci] + ig*gg;
        g_qc[ci]=cn;
        h_out[(b<<7)+u]=og*htanh(cn);
    }
}

__global__ void q_attn_kernel(const float* __restrict__ W, const float* __restrict__ bias){
    __shared__ float Ws[8192];
    int tid=threadIdx.x;
    for (int i=tid;i<8192;i+=256) Ws[i]=0.f;
    __syncthreads();
    for (int i=tid;i<25*256;i+=256){ int o=i>>8,k=i&255; Ws[(k<<5)+o]=W[i]; }
    __syncthreads();
    int lane=tid&31;
    int gw=(blockIdx.x<<3)+(tid>>5);
    if (gw>=288) return;
    int b=gw&31, rt=gw>>5; int r=rt/3, t=rt%3;
    const float* hf = g_qh + ((r*2  )*3 + t    )*4096 + (b<<7);
    const float* hb = g_qh + ((r*2+1)*3 + (2-t))*4096 + (b<<7);
    float acc = (lane<25)? bias[lane] : -1e30f;
    for (int k=0;k<128;k++) acc += hf[k]*Ws[(k<<5)+lane];
    for (int k=0;k<128;k++) acc += hb[k]*Ws[((k+128)<<5)+lane];
    float mx=acc;
    for (int o=16;o;o>>=1) mx=fmaxf(mx,__shfl_xor_sync(0xffffffffu,mx,o));
    float e=(lane<25)?expf(acc-mx):0.f;
    float s=e;
    for (int o=16;o;o>>=1) s+=__shfl_xor_sync(0xffffffffu,s,o);
    if (lane<25) g_qattn[rt*800 + b*25 + lane] = e/s;
}

// ---------------- propagation (CSR gather + fused colsum) ----------------
__global__ void init_sums(){
    int i = threadIdx.x;
    if (i<96){ g_sumsA[i]=1.f; g_sumsB[i]=0.f; }
}

__global__ __launch_bounds__(256) void csr_step(int ab, int t, int t0flag,
                                                const int* __restrict__ heads){
    int r = blockIdx.y;
    __shared__ float qs[800];
    const float* qa = g_qattn + (r*3+t)*800;
    for (int i=threadIdx.x;i<800;i+=256) qs[i]=qa[i];
    __syncthreads();
    const float* inb  = (ab ? g_bufB : g_bufA) + r*NENT*BQ;
    float*       outb = (ab ? g_bufA : g_bufB) + r*NENT*BQ;
    const float* sums =  ab ? g_sumsB : g_sumsA;
    float*       osum =  ab ? g_sumsA : g_sumsB;
    int lane = threadIdx.x&31, wid = threadIdx.x>>5;
    float inv = __fdividef(1.f, fmaxf(1e-20f, sums[r*32+lane]));
    float qlast = qs[lane*25+24];
    int hb = t0flag ? heads[lane] : 0;
    float csum = 0.f;
    int n0 = (blockIdx.x<<6) + (wid<<3);
    #pragma unroll 1
    for (int j=0;j<8;j++){
        int n = n0+j;
        if (n < NENT){
            float acc;
            int s0 = g_offs[n], s1 = g_offs[n+1];
            if (t0flag){
                acc = qlast * ((hb==n)? 1.f : 0.f);
                for (int i=s0;i<s1;i++){
                    int2 en = g_csr[i];
                    float val = qs[lane*25 + (en.x>>17)] * __int_as_float(en.y);
                    acc += ((en.x & 0x1FFFF)==hb) ? val : 0.f;
                }
            } else {
                acc = qlast * inb[(n<<5)+lane];
                for (int i=s0;i<s1;i++){
                    int2 en = g_csr[i];
                    float val = qs[lane*25 + (en.x>>17)] * __int_as_float(en.y);
                    acc += val * inb[((en.x & 0x1FFFF)<<5) + lane];
                }
            }
            float v = acc*inv;
            outb[(n<<5)+lane] = v;
            csum += v;
        }
    }
    __shared__ float sh[8][32];
    sh[wid][lane]=csum;
    __syncthreads();
    if (wid==0){
        float s=0.f;
        #pragma unroll
        for (int i=0;i<8;i++) s+=sh[i][lane];
        atomicAdd(&osum[r*32+lane], s);
    }
}

__global__ void zero_sums(int sel){
    if (threadIdx.x < 96) (sel ? g_sumsB : g_sumsA)[threadIdx.x] = 0.f;
}

__global__ void trans_out(float* __restrict__ out){
    __shared__ float tile[32][33];
    __shared__ float invs[96];
    int tx=threadIdx.x, ty=threadIdx.y;
    if (ty<3) invs[ty*32+tx] = __fdividef(1.f, fmaxf(1e-20f, g_sumsB[ty*32+tx]));
    __syncthreads();
    int n0=blockIdx.x<<5;
    int n=n0+ty;
    float v = 0.f;
    if (n<NENT){
        int i = (n<<5)+tx;
        v = g_bufB[i]*invs[tx] + g_bufB[NENT*BQ+i]*invs[32+tx] + g_bufB[2*NENT*BQ+i]*invs[64+tx];
    }
    tile[ty][tx] = v;
    __syncthreads();
    int nn=n0+tx;
    if (nn<NENT) out[ty*NENT+nn] = tile[tx][ty];
}

// ---------------- host ----------------
extern "C" void kernel_launch(void* const* d_in, const int* in_sizes, int n_in,
                              void* d_out, int out_size){
    const int*   queries=(const int*)d_in[0];
    const int*   heads  =(const int*)d_in[1];
    const int*   rels   =(const int*)d_in[2];
    const int*   t_heads=(const int*)d_in[3];
    const int*   t_tails=(const int*)d_in[4];
    const int*   degs   =(const int*)d_in[5];
    const float* qemb=(const float*)d_in[6];
    const float* eemb=(const float*)d_in[7];
    const float* qWih=(const float*)d_in[8];
    const float* qWhh=(const float*)d_in[9];
    const float* qbih=(const float*)d_in[10];
    const float* qbhh=(const float*)d_in[11];
    const float* eWih=(const float*)d_in[12];
    const float* eWhh=(const float*)d_in[13];
    const float* ebih=(const float*)d_in[14];
    const float* ebhh=(const float*)d_in[15];
    const float* qlW=(const float*)d_in[16];
    const float* qlb=(const float*)d_in[17];
    const float* elW=(const float*)d_in[18];
    const float* elb=(const float*)d_in[19];
    float* out=(float*)d_out;

    cudaFuncSetAttribute(ent_fused, cudaFuncAttributeMaxDynamicSharedMemorySize, DSMEM);

    prep_kernel<<<(PREP_TOT+255)/256,256>>>(eWih,eWhh,ebih,ebhh,eemb,
                                            qWih,qWhh,qbih,qbhh,qemb,queries);
    zero_cnt<<<(NENT+255)/256,256>>>();
    count_k<<<(NEDGE+255)/256,256>>>(t_heads, t_tails);
    scan1<<<NB_SCAN,1024>>>();
    scan2<<<1,64>>>();
    scan3<<<(NENT+255)/256,256>>>();
    scatter_k<<<(NEDGE+255)/256,256>>>(rels, t_heads, t_tails);

    ent_fused<<<dim3(MTILES,2),512,DSMEM>>>(degs);

    ent_attn_kernel<<<1024,256>>>(elW, elb);
    fill_w<<<(NCSR+255)/256,256>>>();

    q_step0<<<96,256>>>();
    q_step<<<dim3(8,6),256>>>(1);
    q_step<<<dim3(8,6),256>>>(2);
    q_attn_kernel<<<36,256>>>(qlW, qlb);

    init_sums<<<1,128>>>();
    csr_step<<<dim3(782,3),256>>>(0, 0, 1, heads);
    zero_sums<<<1,128>>>(0);
    csr_step<<<dim3(782,3),256>>>(1, 1, 0, heads);
    zero_sums<<<1,128>>>(1);
    csr_step<<<dim3(782,3),256>>>(0, 2, 0, heads);
    trans_out<<<1563,dim3(32,32)>>>(out);
}

// round 13
// speedup vs baseline: 1.9096x; 1.0152x over previous
#include <cuda_runtime.h>
#include <cuda_bf16.h>
#include <math.h>
#include <stdint.h>

#define NENT 50000
#define MTILES 391
#define NEDGE 400000
#define NCSR  (2*NEDGE)
#define BQ 32
#define HID 128
#define G4 512
#define NB_SCAN 49

// ---------------- scratch (device globals; no allocation) ----------------
__device__ __align__(16) float g_Ppre[2*25*G4];
__device__ __align__(16) float g_hF[NENT*HID];
__device__ __align__(16) float g_hB[NENT*HID];
__device__ float g_eattn[NENT*24];
__device__ __align__(16) float g_Wqperm[6*G4*HID];
__device__ __align__(16) float g_Pq[6*BQ*G4];
__device__ __align__(16) float g_qh[18*BQ*HID];
__device__ float g_qc[6*BQ*HID];
__device__ float g_qattn[9*BQ*25];
__device__ float g_bufA[3*NENT*BQ];
__device__ float g_bufB[3*NENT*BQ];
__device__ float g_sumsA[96];
__device__ float g_sumsB[96];

// CSR over targets (fwd+rev entries)
__device__ int  g_cnt[NENT];
__device__ int  g_offs[NENT+1];
__device__ int  g_fill[NENT];
__device__ int  g_bsum[64];
__device__ int  g_wind[NCSR];
__device__ __align__(8) int2 g_csr[NCSR];

// B operands (bf16 hi only): [dir(2)][p 512 (perm gate col)][k 128]
__device__ __align__(16) __nv_bfloat16 g_Bmma[2*512*128];

// HW tanh (sm_75+): single MUFU op; sigmoid via identity
__device__ __forceinline__ float htanh(float x){
    float y; asm("tanh.approx.f32 %0, %1;" : "=f"(y) : "f"(x)); return y;
}
__device__ __forceinline__ float hsigm(float x){
    return fmaf(htanh(0.5f*x), 0.5f, 0.5f);
}

__device__ __forceinline__ uint32_t smem_u32(const void* p){
    uint32_t a;
    asm("{ .reg .u64 t; cvta.to.shared.u64 t, %1; cvt.u32.u64 %0, t; }" : "=r"(a) : "l"(p));
    return a;
}

#define LDSM4(r, addr) \
    asm volatile("ldmatrix.sync.aligned.m8n8.x4.shared.b16 {%0,%1,%2,%3}, [%4];" \
        : "=r"((r)[0]),"=r"((r)[1]),"=r"((r)[2]),"=r"((r)[3]) : "r"(addr))

#define MMA16816(d, a, b0, b1) \
    asm volatile("mma.sync.aligned.m16n8k16.row.col.f32.bf16.bf16.f32 " \
        "{%0,%1,%2,%3}, {%4,%5,%6,%7}, {%8,%9}, {%0,%1,%2,%3};" \
        : "+f"((d)[0]),"+f"((d)[1]),"+f"((d)[2]),"+f"((d)[3]) \
        : "r"((a)[0]),"r"((a)[1]),"r"((a)[2]),"r"((a)[3]), "r"(b0),"r"(b1))

#define CPA16(dst, src) asm volatile("cp.async.cg.shared.global [%0], [%1], 16;" :: "r"(dst), "l"(src))
#define CPA_COMMIT()    asm volatile("cp.async.commit_group;" ::: "memory")
#define CPA_WAIT0()     asm volatile("cp.async.wait_group 0;" ::: "memory")

// smem: B 4x32KB at [0,128K); A buf0 at [128K,160K); A buf1 at [160K,192K)
#define SM_A   131072
#define DSMEM  196608

// ---------------- preprocessing ----------------
#define S2 25600
#define S4 393216
#define S5 98304
#define S6 131072
#define PREP_TOT (S2+S4+S5+S6)

__global__ void prep_kernel(const float* __restrict__ eWih, const float* __restrict__ eWhh,
                            const float* __restrict__ ebih, const float* __restrict__ ebhh,
                            const float* __restrict__ eemb,
                            const float* __restrict__ qWih, const float* __restrict__ qWhh,
                            const float* __restrict__ qbih, const float* __restrict__ qbhh,
                            const float* __restrict__ qemb, const int* __restrict__ queries){
    int idx = blockIdx.x*blockDim.x + threadIdx.x;
    if (idx < S2){
        int dir = idx / 12800; int rem = idx % 12800; int v = rem >> 9; int p = rem & 511;
        int j = ((p&3)<<7) + (p>>2);
        float acc = ebih[(dir<<9)+j] + ebhh[(dir<<9)+j];
        const float* wr = eWih + (dir<<16) + (j<<7);
        const float* er = eemb + (v<<7);
        for (int k=0;k<128;k++) acc += er[k]*wr[k];
        g_Ppre[(dir*12800) + (v<<9) + p] = acc;
        return;
    }
    idx -= S2;
    if (idx < S4){
        int pr = idx >> 16; int rem = idx & 65535; int p = rem >> 7; int k = rem & 127;
        int j = ((p&3)<<7) + (p>>2);
        g_Wqperm[idx] = qWhh[(pr<<16) + (j<<7) + k];
        return;
    }
    idx -= S4;
    if (idx < S5){
        int pr = idx >> 14; int rem = idx & 16383; int b = rem >> 9; int p = rem & 511;
        int j = ((p&3)<<7) + (p>>2);
        float acc = qbih[(pr<<9)+j] + qbhh[(pr<<9)+j];
        const float* wr = qWih + (pr<<16) + (j<<7);
        const float* xr = qemb + (queries[b]<<7);
        for (int k=0;k<128;k++) acc += xr[k]*wr[k];
        g_Pq[(pr<<14) + (b<<9) + p] = acc;
        return;
    }
    idx -= S5;
    if (idx < S6){
        int dir = idx >> 16;
        int p = (idx >> 7) & 511;
        int k = idx & 127;
        int q = p & 15, b = p >> 4;
        int u = 4*b + ((q&7)>>1);
        int gate = (q<8) ? (q&1) : 2+(q&1);
        int j = (gate<<7) + u;
        g_Bmma[idx] = __float2bfloat16(eWhh[(dir<<16) + (j<<7) + k]);
    }
}

// ---------------- CSR build ----------------
__global__ void zero_cnt(){
    int i = blockIdx.x*blockDim.x + threadIdx.x;
    if (i < NENT) g_cnt[i] = 0;
}
__global__ void count_k(const int* __restrict__ th, const int* __restrict__ tt){
    int e = blockIdx.x*blockDim.x + threadIdx.x;
    if (e >= NEDGE) return;
    atomicAdd(&g_cnt[tt[e]], 1);
    atomicAdd(&g_cnt[th[e]], 1);
}
__global__ void scan1(){
    __shared__ int sh[1024];
    int i = blockIdx.x*1024 + threadIdx.x;
    int v = (i<NENT)? g_cnt[i] : 0;
    sh[threadIdx.x]=v;
    __syncthreads();
    for (int off=1; off<1024; off<<=1){
        int t = (threadIdx.x>=off)? sh[threadIdx.x-off] : 0;
        __syncthreads();
        sh[threadIdx.x]+=t;
        __syncthreads();
    }
    if (i<NENT) g_offs[i] = sh[threadIdx.x]-v;
    if (threadIdx.x==1023) g_bsum[blockIdx.x]=sh[1023];
}
__global__ void scan2(){
    __shared__ int sh[64];
    int v = (threadIdx.x<NB_SCAN)? g_bsum[threadIdx.x] : 0;
    sh[threadIdx.x]=v;
    __syncthreads();
    for (int off=1; off<64; off<<=1){
        int t = (threadIdx.x>=off)? sh[threadIdx.x-off] : 0;
        __syncthreads();
        sh[threadIdx.x]+=t;
        __syncthreads();
    }
    if (threadIdx.x<NB_SCAN) g_bsum[threadIdx.x] = sh[threadIdx.x]-v;
    if (threadIdx.x==NB_SCAN-1) g_bsum[63] = sh[NB_SCAN-1];
}
__global__ void scan3(){
    int i = blockIdx.x*blockDim.x + threadIdx.x;
    if (i<NENT){
        int v = g_offs[i] + g_bsum[i>>10];
        g_offs[i]=v;
        g_fill[i]=v;
    }
    if (i==0) g_offs[NENT] = g_bsum[63];
}
__global__ void scatter_k(const int* __restrict__ rl, const int* __restrict__ th,
                          const int* __restrict__ tt){
    int e = blockIdx.x*blockDim.x + threadIdx.x;
    if (e >= NEDGE) return;
    int h = th[e], t2 = tt[e], r = rl[e];
    int wind = h*24 + r;
    int p1 = atomicAdd(&g_fill[t2], 1);
    g_csr[p1].x = h | (r<<17);
    g_wind[p1] = wind;
    int p2 = atomicAdd(&g_fill[h], 1);
    g_csr[p2].x = t2 | ((r+12)<<17);
    g_wind[p2] = wind;
}
__global__ void fill_w(){
    int i = blockIdx.x*blockDim.x + threadIdx.x;
    if (i >= NCSR) return;
    g_csr[i].y = __float_as_int(g_eattn[g_wind[i]]);
}

// ---------------- fused entity BiLSTM (single bf16 A plane, double-buffered) ----------------
__global__ __launch_bounds__(512) void ent_fused(const int* __restrict__ degs){
    extern __shared__ __align__(16) char sm[];
    uint32_t sb = smem_u32(sm);
    int tid = threadIdx.x, lane = tid&31, wid = tid>>5;
    int warpM = wid&3, warpN = (wid>>2)&3;
    int mt = blockIdx.x, dir = blockIdx.y;
    int mbase = mt*128;

    #pragma unroll
    for (int j=0;j<16;j++){
        int i = tid + (j<<9);
        int p = i>>4, c = i&15;
        uint32_t dst = sb + ((p>>7)<<15) + ((p&127)<<8) + (((c ^ (p&7)))<<4);
        const void* src = g_Bmma + ((size_t)(dir<<9) + p)*128 + c*8;
        CPA16(dst, src);
    }
    CPA_COMMIT();

    int tg = lane>>2, tc = lane&3;
    int rows[4];
    #pragma unroll
    for (int mi=0;mi<2;mi++)
        #pragma unroll
        for (int rh=0;rh<2;rh++)
            rows[mi*2+rh] = warpM*32 + mi*16 + rh*8 + tg;

    float c_reg[4][8];
    const float* Pdir = g_Ppre + dir*12800;
    float* gH = dir ? g_hB : g_hF;

    {   // step 0 -> write h into A buf0
        int t0 = dir ? 7 : 0;
        #pragma unroll
        for (int r4=0;r4<4;r4++){
            int row = rows[r4];
            int m = mbase + row;
            bool mv = (m < NENT);
            int d = mv ? degs[(m<<3)+t0] : 0;
            const float4* Pb = (const float4*)(Pdir + (d<<9));
            #pragma unroll
            for (int ch=0;ch<4;ch++){
                #pragma unroll
                for (int nt2=0;nt2<2;nt2++){
                    int u = ch*32 + warpN*8 + nt2*4 + tc;
                    float4 P = Pb[u];
                    float cn = hsigm(P.x)*htanh(P.z);
                    float h  = hsigm(P.w)*htanh(cn);
                    c_reg[ch][r4*2+nt2] = cn;
                    uint32_t off = (row<<8) + ((((u>>3) ^ (row&7)))<<4) + ((u&7)<<1);
                    *(__nv_bfloat16*)(sm + SM_A + off) = __float2bfloat16(h);
                }
            }
        }
    }
    CPA_WAIT0();
    __syncthreads();

    int aRowBase = warpM*32 + (lane&7) + ((lane>>3)&1)*8;
    int aHi = lane>>4;
    int bRowBase = warpN*32 + (lane&7) + (lane>>4)*8;
    int bHi = (lane>>3)&1;

    #pragma unroll 1
    for (int s=1;s<8;s++){
        int t = dir ? 7-s : s;
        uint32_t aP = sb + SM_A + (((s-1)&1)<<15);     // read buffer
        char* wB = sm + SM_A + ((s&1)<<15);            // write buffer
        #pragma unroll
        for (int ch=0;ch<4;ch++){
            float acc[2][4][4];
            #pragma unroll
            for (int a1=0;a1<2;a1++)
                #pragma unroll
                for (int a2=0;a2<4;a2++)
                    #pragma unroll
                    for (int a3=0;a3<4;a3++) acc[a1][a2][a3]=0.f;

            uint32_t bP = sb + (ch<<15);
            #pragma unroll
            for (int kc=0;kc<8;kc++){
                uint32_t afr[2][4], bfr[2][4];
                #pragma unroll
                for (int mi=0;mi<2;mi++){
                    int r = aRowBase + mi*16;
                    LDSM4(afr[mi], aP + (r<<8) + (((2*kc + aHi) ^ (r&7))<<4));
                }
                #pragma unroll
                for (int nt2=0;nt2<2;nt2++){
                    int r = bRowBase + nt2*16;
                    LDSM4(bfr[nt2], bP + (r<<8) + (((2*kc + bHi) ^ (r&7))<<4));
                }
                #pragma unroll
                for (int mi=0;mi<2;mi++)
                    #pragma unroll
                    for (int nt2=0;nt2<2;nt2++){
                        MMA16816(acc[mi][2*nt2],   afr[mi], bfr[nt2][0], bfr[nt2][1]);
                        MMA16816(acc[mi][2*nt2+1], afr[mi], bfr[nt2][2], bfr[nt2][3]);
                    }
            }
            #pragma unroll
            for (int mi=0;mi<2;mi++){
                #pragma unroll
                for (int rh=0;rh<2;rh++){
                    int r4 = mi*2+rh;
                    int row = rows[r4];
                    int m = mbase + row;
                    bool mv = (m < NENT);
                    int d = mv ? degs[(m<<3)+t] : 0;
                    const float4* Pb = (const float4*)(Pdir + (d<<9));
                    #pragma unroll
                    for (int nt2=0;nt2<2;nt2++){
                        int u = ch*32 + warpN*8 + nt2*4 + tc;
                        float4 P = Pb[u];
                        float ig = hsigm(acc[mi][2*nt2  ][rh*2+0] + P.x);
                        float fg = hsigm(acc[mi][2*nt2  ][rh*2+1] + P.y);
                        float gg = htanh(acc[mi][2*nt2+1][rh*2+0] + P.z);
                        float og = hsigm(acc[mi][2*nt2+1][rh*2+1] + P.w);
                        float cn = fg*c_reg[ch][r4*2+nt2] + ig*gg;
                        c_reg[ch][r4*2+nt2] = cn;
                        float h = og*htanh(cn);
                        if (s==7){
                            if (mv) gH[(m<<7)+u] = h;
                        } else {
                            uint32_t off = (row<<8) + ((((u>>3) ^ (row&7)))<<4) + ((u&7)<<1);
                            *(__nv_bfloat16*)(wB + off) = __float2bfloat16(h);
                        }
                    }
                }
            }
        }
        if (s<7) __syncthreads();    // single barrier per step
    }
}

// ---------------- entity attention ----------------
__global__ void ent_attn_kernel(const float* __restrict__ W, const float* __restrict__ bias){
    __shared__ float Ws[8192];
    int tid = threadIdx.x;
    for (int i=tid;i<8192;i+=256) Ws[i]=0.f;
    __syncthreads();
    for (int i=tid;i<24*256;i+=256){ int o=i>>8, k=i&255; Ws[(k<<5)+o]=W[i]; }
    __syncthreads();
    int lane = tid&31;
    int wid = (blockIdx.x<<3) + (tid>>5);
    int nw  = gridDim.x<<3;
    float bv = (lane<24)? bias[lane] : -1e30f;
    for (int n=wid; n<NENT; n+=nw){
        float acc = bv;
        const float* hf = g_hF + (n<<7);
        const float* hb = g_hB + (n<<7);
        for (int k=0;k<128;k++) acc += hf[k]*Ws[(k<<5)+lane];
        for (int k=0;k<128;k++) acc += hb[k]*Ws[((k+128)<<5)+lane];
        float mx = acc;
        for (int o=16;o;o>>=1) mx = fmaxf(mx, __shfl_xor_sync(0xffffffffu, mx, o));
        float e = (lane<24)? expf(acc-mx) : 0.f;
        float s = e;
        for (int o=16;o;o>>=1) s += __shfl_xor_sync(0xffffffffu, s, o);
        if (lane<24) g_eattn[n*24+lane] = e/s;
    }
}

// ---------------- query LSTMs ----------------
__global__ void q_step0(){
    int idx = blockIdx.x*blockDim.x + threadIdx.x;
    if (idx >= 6*BQ*HID) return;
    int pr = idx/4096; int rem = idx&4095; int b = rem>>7; int u = rem&127;
    float4 P = *(const float4*)(g_Pq + (pr<<14) + (b<<9) + (u<<2));
    float cn = hsigm(P.x)*htanh(P.z);
    g_qc[idx] = cn;
    g_qh[pr*3*4096 + rem] = hsigm(P.w)*htanh(cn);
}

__global__ __launch_bounds__(256) void q_step(int s){
    int pr = blockIdx.y;
    int cb = blockIdx.x<<6;
    const float* h_in = g_qh + (pr*3 + s-1)*4096;
    float* h_out      = g_qh + (pr*3 + s)*4096;
    __shared__ float As[16][36];
    __shared__ float Bs[16][68];
    int tid=threadIdx.x;
    int ty=tid>>4, tx=tid&15;
    const float* Wp = g_Wqperm + (pr<<16);
    float acc[2][4] = {};
    int lrA = tid>>3; int kqA = (tid&7)<<1;
    int lrB = tid>>2; int kqB = (tid&3)<<2;
    for (int kb=0;kb<128;kb+=16){
        float2 a2 = *(const float2*)(h_in + (lrA<<7) + kb + kqA);
        float4 b4 = *(const float4*)(Wp + ((cb+lrB)<<7) + kb + kqB);
        As[kqA+0][lrA]=a2.x; As[kqA+1][lrA]=a2.y;
        Bs[kqB+0][lrB]=b4.x; Bs[kqB+1][lrB]=b4.y; Bs[kqB+2][lrB]=b4.z; Bs[kqB+3][lrB]=b4.w;
        __syncthreads();
        #pragma unroll
        for (int k=0;k<16;k++){
            float a0=As[k][(ty<<1)], a1=As[k][(ty<<1)+1];
            float4 b=*(const float4*)&Bs[k][tx<<2];
            acc[0][0]+=a0*b.x; acc[0][1]+=a0*b.y; acc[0][2]+=a0*b.z; acc[0][3]+=a0*b.w;
            acc[1][0]+=a1*b.x; acc[1][1]+=a1*b.y; acc[1][2]+=a1*b.z; acc[1][3]+=a1*b.w;
        }
        __syncthreads();
    }
    int u = (cb>>2)+tx;
    #pragma unroll
    for (int i=0;i<2;i++){
        int b = (ty<<1)+i;
        float4 P = *(const float4*)(g_Pq + (pr<<14) + (b<<9) + cb + (tx<<2));
        float ig=hsigm(acc[i][0]+P.x), fg=hsigm(acc[i][1]+P.y);
        float gg=htanh(acc[i][2]+P.z), og=hsigm(acc[i][3]+P.w);
        int ci = pr*4096 + (b<<7) + u;
        float cn = fg*g_qc[ci] + ig*gg;
        g_qc[ci]=cn;
        h_out[(b<<7)+u]=og*htanh(cn);
    }
}

__global__ void q_attn_kernel(const float* __restrict__ W, const float* __restrict__ bias){
    __shared__ float Ws[8192];
    int tid=threadIdx.x;
    for (int i=tid;i<8192;i+=256) Ws[i]=0.f;
    __syncthreads();
    for (int i=tid;i<25*256;i+=256){ int o=i>>8,k=i&255; Ws[(k<<5)+o]=W[i]; }
    __syncthreads();
    int lane=tid&31;
    int gw=(blockIdx.x<<3)+(tid>>5);
    if (gw>=288) return;
    int b=gw&31, rt=gw>>5; int r=rt/3, t=rt%3;
    const float* hf = g_qh + ((r*2  )*3 + t    )*4096 + (b<<7);
    const float* hb = g_qh + ((r*2+1)*3 + (2-t))*4096 + (b<<7);
    float acc = (lane<25)? bias[lane] : -1e30f;
    for (int k=0;k<128;k++) acc += hf[k]*Ws[(k<<5)+lane];
    for (int k=0;k<128;k++) acc += hb[k]*Ws[((k+128)<<5)+lane];
    float mx=acc;
    for (int o=16;o;o>>=1) mx=fmaxf(mx,__shfl_xor_sync(0xffffffffu,mx,o));
    float e=(lane<25)?expf(acc-mx):0.f;
    float s=e;
    for (int o=16;o;o>>=1) s+=__shfl_xor_sync(0xffffffffu,s,o);
    if (lane<25) g_qattn[rt*800 + b*25 + lane] = e/s;
}

// ---------------- propagation (CSR gather + fused colsum) ----------------
__global__ void init_sums(){
    int i = threadIdx.x;
    if (i<96){ g_sumsA[i]=1.f; g_sumsB[i]=0.f; }
}

__global__ __launch_bounds__(256) void csr_step(int ab, int t, int t0flag,
                                                const int* __restrict__ heads){
    int r = blockIdx.y;
    __shared__ float qs[800];
    const float* qa = g_qattn + (r*3+t)*800;
    for (int i=threadIdx.x;i<800;i+=256) qs[i]=qa[i];
    __syncthreads();
    const float* inb  = (ab ? g_bufB : g_bufA) + r*NENT*BQ;
    float*       outb = (ab ? g_bufA : g_bufB) + r*NENT*BQ;
    const float* sums =  ab ? g_sumsB : g_sumsA;
    float*       osum =  ab ? g_sumsA : g_sumsB;
    int lane = threadIdx.x&31, wid = threadIdx.x>>5;
    float inv = __fdividef(1.f, fmaxf(1e-20f, sums[r*32+lane]));
    float qlast = qs[lane*25+24];
    int hb = t0flag ? heads[lane] : 0;
    float csum = 0.f;
    int n0 = (blockIdx.x<<6) + (wid<<3);
    #pragma unroll 1
    for (int j=0;j<8;j++){
        int n = n0+j;
        if (n < NENT){
            float acc;
            int s0 = g_offs[n], s1 = g_offs[n+1];
            if (t0flag){
                acc = qlast * ((hb==n)? 1.f : 0.f);
                for (int i=s0;i<s1;i++){
                    int2 en = g_csr[i];
                    float val = qs[lane*25 + (en.x>>17)] * __int_as_float(en.y);
                    acc += ((en.x & 0x1FFFF)==hb) ? val : 0.f;
                }
            } else {
                acc = qlast * inb[(n<<5)+lane];
                for (int i=s0;i<s1;i++){
                    int2 en = g_csr[i];
                    float val = qs[lane*25 + (en.x>>17)] * __int_as_float(en.y);
                    acc += val * inb[((en.x & 0x1FFFF)<<5) + lane];
                }
            }
            float v = acc*inv;
            outb[(n<<5)+lane] = v;
            csum += v;
        }
    }
    __shared__ float sh[8][32];
    sh[wid][lane]=csum;
    __syncthreads();
    if (wid==0){
        float s=0.f;
        #pragma unroll
        for (int i=0;i<8;i++) s+=sh[i][lane];
        atomicAdd(&osum[r*32+lane], s);
    }
}

__global__ void zero_sums(int sel){
    if (threadIdx.x < 96) (sel ? g_sumsB : g_sumsA)[threadIdx.x] = 0.f;
}

__global__ void trans_out(float* __restrict__ out){
    __shared__ float tile[32][33];
    __shared__ float invs[96];
    int tx=threadIdx.x, ty=threadIdx.y;
    if (ty<3) invs[ty*32+tx] = __fdividef(1.f, fmaxf(1e-20f, g_sumsB[ty*32+tx]));
    __syncthreads();
    int n0=blockIdx.x<<5;
    int n=n0+ty;
    float v = 0.f;
    if (n<NENT){
        int i = (n<<5)+tx;
        v = g_bufB[i]*invs[tx] + g_bufB[NENT*BQ+i]*invs[32+tx] + g_bufB[2*NENT*BQ+i]*invs[64+tx];
    }
    tile[ty][tx] = v;
    __syncthreads();
    int nn=n0+tx;
    if (nn<NENT) out[ty*NENT+nn] = tile[tx][ty];
}

// ---------------- host ----------------
extern "C" void kernel_launch(void* const* d_in, const int* in_sizes, int n_in,
                              void* d_out, int out_size){
    const int*   queries=(const int*)d_in[0];
    const int*   heads  =(const int*)d_in[1];
    const int*   rels   =(const int*)d_in[2];
    const int*   t_heads=(const int*)d_in[3];
    const int*   t_tails=(const int*)d_in[4];
    const int*   degs   =(const int*)d_in[5];
    const float* qemb=(const float*)d_in[6];
    const float* eemb=(const float*)d_in[7];
    const float* qWih=(const float*)d_in[8];
    const float* qWhh=(const float*)d_in[9];
    const float* qbih=(const float*)d_in[10];
    const float* qbhh=(const float*)d_in[11];
    const float* eWih=(const float*)d_in[12];
    const float* eWhh=(const float*)d_in[13];
    const float* ebih=(const float*)d_in[14];
    const float* ebhh=(const float*)d_in[15];
    const float* qlW=(const float*)d_in[16];
    const float* qlb=(const float*)d_in[17];
    const float* elW=(const float*)d_in[18];
    const float* elb=(const float*)d_in[19];
    float* out=(float*)d_out;

    cudaFuncSetAttribute(ent_fused, cudaFuncAttributeMaxDynamicSharedMemorySize, DSMEM);

    // launch order puts ent_fused 4th => ncu (-s bound) captures it
    prep_kernel<<<(PREP_TOT+255)/256,256>>>(eWih,eWhh,ebih,ebhh,eemb,
                                            qWih,qWhh,qbih,qbhh,qemb,queries);
    zero_cnt<<<(NENT+255)/256,256>>>();
    count_k<<<(NEDGE+255)/256,256>>>(t_heads, t_tails);

    ent_fused<<<dim3(MTILES,2),512,DSMEM>>>(degs);   // 4th launch

    scan1<<<NB_SCAN,1024>>>();
    scan2<<<1,64>>>();
    scan3<<<(NENT+255)/256,256>>>();
    scatter_k<<<(NEDGE+255)/256,256>>>(rels, t_heads, t_tails);

    ent_attn_kernel<<<1024,256>>>(elW, elb);
    fill_w<<<(NCSR+255)/256,256>>>();

    q_step0<<<96,256>>>();
    q_step<<<dim3(8,6),256>>>(1);
    q_step<<<dim3(8,6),256>>>(2);
    q_attn_kernel<<<36,256>>>(qlW, qlb);

    init_sums<<<1,128>>>();
    csr_step<<<dim3(782,3),256>>>(0, 0, 1, heads);
    zero_sums<<<1,128>>>(0);
    csr_step<<<dim3(782,3),256>>>(1, 1, 0, heads);
    zero_sums<<<1,128>>>(1);
    csr_step<<<dim3(782,3),256>>>(0, 2, 0, heads);
    trans_out<<<1563,dim3(32,32)>>>(out);
}

// round 15
// speedup vs baseline: 2.1190x; 1.1096x over previous
#include <cuda_runtime.h>
#include <cuda_bf16.h>
#include <math.h>
#include <stdint.h>

#define NENT 50000
#define MTILES 391
#define NEDGE 400000
#define NCSR  (2*NEDGE)
#define BQ 32
#define HID 128
#define G4 512
#define NB_SCAN 49

// ---------------- scratch (device globals; no allocation) ----------------
__device__ __align__(16) float g_Ppre[2*25*G4];
__device__ __align__(16) float g_hF[NENT*HID];
__device__ __align__(16) float g_hB[NENT*HID];
__device__ float g_eattn[NENT*24];
__device__ __align__(16) float g_Wqperm[6*G4*HID];
__device__ __align__(16) float g_Pq[6*BQ*G4];
__device__ __align__(16) float g_qh[18*BQ*HID];
__device__ float g_qc[6*BQ*HID];
__device__ float g_qattn[9*BQ*25];
__device__ float g_bufA[3*NENT*BQ];
__device__ float g_bufB[3*NENT*BQ];
__device__ float g_sumsA[96];
__device__ float g_sumsB[96];

// CSR over targets (fwd+rev entries)
__device__ int  g_cnt[NENT];
__device__ int  g_offs[NENT+1];
__device__ int  g_fill[NENT];
__device__ int  g_bsum[64];
__device__ int  g_wind[NCSR];
__device__ __align__(8) int2 g_csr[NCSR];

// B operands (bf16 hi only): [dir(2)][p 512 (perm gate col)][k 128]
__device__ __align__(16) __nv_bfloat16 g_Bmma[2*512*128];

__device__ __forceinline__ float htanh(float x){
    float y; asm("tanh.approx.f32 %0, %1;" : "=f"(y) : "f"(x)); return y;
}
__device__ __forceinline__ float hsigm(float x){
    return fmaf(htanh(0.5f*x), 0.5f, 0.5f);
}

__device__ __forceinline__ uint32_t smem_u32(const void* p){
    uint32_t a;
    asm("{ .reg .u64 t; cvta.to.shared.u64 t, %1; cvt.u32.u64 %0, t; }" : "=r"(a) : "l"(p));
    return a;
}

#define LDSM4(r, addr) \
    asm volatile("ldmatrix.sync.aligned.m8n8.x4.shared.b16 {%0,%1,%2,%3}, [%4];" \
        : "=r"((r)[0]),"=r"((r)[1]),"=r"((r)[2]),"=r"((r)[3]) : "r"(addr))

#define MMA16816(d, a, b0, b1) \
    asm volatile("mma.sync.aligned.m16n8k16.row.col.f32.bf16.bf16.f32 " \
        "{%0,%1,%2,%3}, {%4,%5,%6,%7}, {%8,%9}, {%0,%1,%2,%3};" \
        : "+f"((d)[0]),"+f"((d)[1]),"+f"((d)[2]),"+f"((d)[3]) \
        : "r"((a)[0]),"r"((a)[1]),"r"((a)[2]),"r"((a)[3]), "r"(b0),"r"(b1))

#define CPA16(dst, src) asm volatile("cp.async.cg.shared.global [%0], [%1], 16;" :: "r"(dst), "l"(src))
#define CPA_COMMIT()    asm volatile("cp.async.commit_group;" ::: "memory")
#define CPA_WAIT0()     asm volatile("cp.async.wait_group 0;" ::: "memory")

// smem: B 4x32KB at [0,128K); A buf0 at [128K,160K); A buf1 at [160K,192K)
#define SM_A   131072
#define DSMEM  196608

// ---------------- preprocessing ----------------
#define S2 25600
#define S4 393216
#define S5 98304
#define S6 131072
#define PREP_TOT (S2+S4+S5+S6)

__global__ void prep_kernel(const float* __restrict__ eWih, const float* __restrict__ eWhh,
                            const float* __restrict__ ebih, const float* __restrict__ ebhh,
                            const float* __restrict__ eemb,
                            const float* __restrict__ qWih, const float* __restrict__ qWhh,
                            const float* __restrict__ qbih, const float* __restrict__ qbhh,
                            const float* __restrict__ qemb, const int* __restrict__ queries){
    int idx = blockIdx.x*blockDim.x + threadIdx.x;
    if (idx < S2){
        int dir = idx / 12800; int rem = idx % 12800; int v = rem >> 9; int p = rem & 511;
        int j = ((p&3)<<7) + (p>>2);
        float acc = ebih[(dir<<9)+j] + ebhh[(dir<<9)+j];
        const float* wr = eWih + (dir<<16) + (j<<7);
        const float* er = eemb + (v<<7);
        for (int k=0;k<128;k++) acc += er[k]*wr[k];
        g_Ppre[(dir*12800) + (v<<9) + p] = acc;
        return;
    }
    idx -= S2;
    if (idx < S4){
        int pr = idx >> 16; int rem = idx & 65535; int p = rem >> 7; int k = rem & 127;
        int j = ((p&3)<<7) + (p>>2);
        g_Wqperm[idx] = qWhh[(pr<<16) + (j<<7) + k];
        return;
    }
    idx -= S4;
    if (idx < S5){
        int pr = idx >> 14; int rem = idx & 16383; int b = rem >> 9; int p = rem & 511;
        int j = ((p&3)<<7) + (p>>2);
        float acc = qbih[(pr<<9)+j] + qbhh[(pr<<9)+j];
        const float* wr = qWih + (pr<<16) + (j<<7);
        const float* xr = qemb + (queries[b]<<7);
        for (int k=0;k<128;k++) acc += xr[k]*wr[k];
        g_Pq[(pr<<14) + (b<<9) + p] = acc;
        return;
    }
    idx -= S5;
    if (idx < S6){
        int dir = idx >> 16;
        int p = (idx >> 7) & 511;
        int k = idx & 127;
        int q = p & 15, b = p >> 4;
        int u = 4*b + ((q&7)>>1);
        int gate = (q<8) ? (q&1) : 2+(q&1);
        int j = (gate<<7) + u;
        g_Bmma[idx] = __float2bfloat16(eWhh[(dir<<16) + (j<<7) + k]);
    }
}

// ---------------- CSR build ----------------
__global__ void zero_cnt(){
    int i = blockIdx.x*blockDim.x + threadIdx.x;
    if (i < NENT) g_cnt[i] = 0;
}
__global__ void count_k(const int* __restrict__ th, const int* __restrict__ tt){
    int e = blockIdx.x*blockDim.x + threadIdx.x;
    if (e >= NEDGE) return;
    atomicAdd(&g_cnt[tt[e]], 1);
    atomicAdd(&g_cnt[th[e]], 1);
}
__global__ void scan1(){
    __shared__ int sh[1024];
    int i = blockIdx.x*1024 + threadIdx.x;
    int v = (i<NENT)? g_cnt[i] : 0;
    sh[threadIdx.x]=v;
    __syncthreads();
    for (int off=1; off<1024; off<<=1){
        int t = (threadIdx.x>=off)? sh[threadIdx.x-off] : 0;
        __syncthreads();
        sh[threadIdx.x]+=t;
        __syncthreads();
    }
    if (i<NENT) g_offs[i] = sh[threadIdx.x]-v;
    if (threadIdx.x==1023) g_bsum[blockIdx.x]=sh[1023];
}
__global__ void scan2(){
    __shared__ int sh[64];
    int v = (threadIdx.x<NB_SCAN)? g_bsum[threadIdx.x] : 0;
    sh[threadIdx.x]=v;
    __syncthreads();
    for (int off=1; off<64; off<<=1){
        int t = (threadIdx.x>=off)? sh[threadIdx.x-off] : 0;
        __syncthreads();
        sh[threadIdx.x]+=t;
        __syncthreads();
    }
    if (threadIdx.x<NB_SCAN) g_bsum[threadIdx.x] = sh[threadIdx.x]-v;
    if (threadIdx.x==NB_SCAN-1) g_bsum[63] = sh[NB_SCAN-1];
}
__global__ void scan3(){
    int i = blockIdx.x*blockDim.x + threadIdx.x;
    if (i<NENT){
        int v = g_offs[i] + g_bsum[i>>10];
        g_offs[i]=v;
        g_fill[i]=v;
    }
    if (i==0) g_offs[NENT] = g_bsum[63];
}
__global__ void scatter_k(const int* __restrict__ rl, const int* __restrict__ th,
                          const int* __restrict__ tt){
    int e = blockIdx.x*blockDim.x + threadIdx.x;
    if (e >= NEDGE) return;
    int h = th[e], t2 = tt[e], r = rl[e];
    int wind = h*24 + r;
    int p1 = atomicAdd(&g_fill[t2], 1);
    g_csr[p1].x = h | (r<<17);
    g_wind[p1] = wind;
    int p2 = atomicAdd(&g_fill[h], 1);
    g_csr[p2].x = t2 | ((r+12)<<17);
    g_wind[p2] = wind;
}
__global__ void fill_w(){
    int i = blockIdx.x*blockDim.x + threadIdx.x;
    if (i >= NCSR) return;
    g_csr[i].y = __float_as_int(g_eattn[g_wind[i]]);
}

// ---------------- fused entity BiLSTM (single bf16 A plane, double-buffered) ----------------
__global__ __launch_bounds__(512) void ent_fused(const int* __restrict__ degs){
    extern __shared__ __align__(16) char sm[];
    uint32_t sb = smem_u32(sm);
    int tid = threadIdx.x, lane = tid&31, wid = tid>>5;
    int warpM = wid&3, warpN = (wid>>2)&3;
    int mt = blockIdx.x, dir = blockIdx.y;
    int mbase = mt*128;

    #pragma unroll
    for (int j=0;j<16;j++){
        int i = tid + (j<<9);
        int p = i>>4, c = i&15;
        uint32_t dst = sb + ((p>>7)<<15) + ((p&127)<<8) + (((c ^ (p&7)))<<4);
        const void* src = g_Bmma + ((size_t)(dir<<9) + p)*128 + c*8;
        CPA16(dst, src);
    }
    CPA_COMMIT();

    int tg = lane>>2, tc = lane&3;
    int rows[4];
    #pragma unroll
    for (int mi=0;mi<2;mi++)
        #pragma unroll
        for (int rh=0;rh<2;rh++)
            rows[mi*2+rh] = warpM*32 + mi*16 + rh*8 + tg;

    float c_reg[4][8];
    const float* Pdir = g_Ppre + dir*12800;
    float* gH = dir ? g_hB : g_hF;

    {   // step 0 -> write h into A buf0
        int t0 = dir ? 7 : 0;
        #pragma unroll
        for (int r4=0;r4<4;r4++){
            int row = rows[r4];
            int m = mbase + row;
            bool mv = (m < NENT);
            int d = mv ? degs[(m<<3)+t0] : 0;
            const float4* Pb = (const float4*)(Pdir + (d<<9));
            #pragma unroll
            for (int ch=0;ch<4;ch++){
                #pragma unroll
                for (int nt2=0;nt2<2;nt2++){
                    int u = ch*32 + warpN*8 + nt2*4 + tc;
                    float4 P = Pb[u];
                    float cn = hsigm(P.x)*htanh(P.z);
                    float h  = hsigm(P.w)*htanh(cn);
                    c_reg[ch][r4*2+nt2] = cn;
                    uint32_t off = (row<<8) + ((((u>>3) ^ (row&7)))<<4) + ((u&7)<<1);
                    *(__nv_bfloat16*)(sm + SM_A + off) = __float2bfloat16(h);
                }
            }
        }
    }
    CPA_WAIT0();
    __syncthreads();

    int aRowBase = warpM*32 + (lane&7) + ((lane>>3)&1)*8;
    int aHi = lane>>4;
    int bRowBase = warpN*32 + (lane&7) + (lane>>4)*8;
    int bHi = (lane>>3)&1;

    #pragma unroll 1
    for (int s=1;s<8;s++){
        int t = dir ? 7-s : s;
        uint32_t aP = sb + SM_A + (((s-1)&1)<<15);
        char* wB = sm + SM_A + ((s&1)<<15);
        // hoist degs per step (same for all chunks)
        int d4[4];
        #pragma unroll
        for (int r4=0;r4<4;r4++){
            int m = mbase + rows[r4];
            d4[r4] = (m < NENT) ? degs[(m<<3)+t] : 0;
        }
        #pragma unroll
        for (int ch=0;ch<4;ch++){
            float acc[2][4][4];
            #pragma unroll
            for (int a1=0;a1<2;a1++)
                #pragma unroll
                for (int a2=0;a2<4;a2++)
                    #pragma unroll
                    for (int a3=0;a3<4;a3++) acc[a1][a2][a3]=0.f;

            uint32_t bP = sb + (ch<<15);
            #pragma unroll
            for (int kc=0;kc<8;kc++){
                uint32_t afr[2][4], bfr[2][4];
                #pragma unroll
                for (int mi=0;mi<2;mi++){
                    int r = aRowBase + mi*16;
                    LDSM4(afr[mi], aP + (r<<8) + (((2*kc + aHi) ^ (r&7))<<4));
                }
                #pragma unroll
                for (int nt2=0;nt2<2;nt2++){
                    int r = bRowBase + nt2*16;
                    LDSM4(bfr[nt2], bP + (r<<8) + (((2*kc + bHi) ^ (r&7))<<4));
                }
                #pragma unroll
                for (int mi=0;mi<2;mi++)
                    #pragma unroll
                    for (int nt2=0;nt2<2;nt2++){
                        MMA16816(acc[mi][2*nt2],   afr[mi], bfr[nt2][0], bfr[nt2][1]);
                        MMA16816(acc[mi][2*nt2+1], afr[mi], bfr[nt2][2], bfr[nt2][3]);
                    }
            }
            #pragma unroll
            for (int mi=0;mi<2;mi++){
                #pragma unroll
                for (int rh=0;rh<2;rh++){
                    int r4 = mi*2+rh;
                    int row = rows[r4];
                    int m = mbase + row;
                    bool mv = (m < NENT);
                    const float4* Pb = (const float4*)(Pdir + (d4[r4]<<9));
                    #pragma unroll
                    for (int nt2=0;nt2<2;nt2++){
                        int u = ch*32 + warpN*8 + nt2*4 + tc;
                        float4 P = Pb[u];
                        float ig = hsigm(acc[mi][2*nt2  ][rh*2+0] + P.x);
                        float fg = hsigm(acc[mi][2*nt2  ][rh*2+1] + P.y);
                        float gg = htanh(acc[mi][2*nt2+1][rh*2+0] + P.z);
                        float og = hsigm(acc[mi][2*nt2+1][rh*2+1] + P.w);
                        float cn = fg*c_reg[ch][r4*2+nt2] + ig*gg;
                        c_reg[ch][r4*2+nt2] = cn;
                        float h = og*htanh(cn);
                        if (s==7){
                            if (mv) gH[(m<<7)+u] = h;
                        } else {
                            uint32_t off = (row<<8) + ((((u>>3) ^ (row&7)))<<4) + ((u&7)<<1);
                            *(__nv_bfloat16*)(wB + off) = __float2bfloat16(h);
                        }
                    }
                }
            }
        }
        if (s<7) __syncthreads();
    }
}

// ---------------- entity attention ----------------
__global__ void ent_attn_kernel(const float* __restrict__ W, const float* __restrict__ bias){
    __shared__ float Ws[8192];
    int tid = threadIdx.x;
    for (int i=tid;i<8192;i+=256) Ws[i]=0.f;
    __syncthreads();
    for (int i=tid;i<24*256;i+=256){ int o=i>>8, k=i&255; Ws[(k<<5)+o]=W[i]; }
    __syncthreads();
    int lane = tid&31;
    int wid = (blockIdx.x<<3) + (tid>>5);
    int nw  = gridDim.x<<3;
    float bv = (lane<24)? bias[lane] : -1e30f;
    for (int n=wid; n<NENT; n+=nw){
        float acc = bv;
        const float* hf = g_hF + (n<<7);
        const float* hb = g_hB + (n<<7);
        for (int k=0;k<128;k++) acc += hf[k]*Ws[(k<<5)+lane];
        for (int k=0;k<128;k++) acc += hb[k]*Ws[((k+128)<<5)+lane];
        float mx = acc;
        for (int o=16;o;o>>=1) mx = fmaxf(mx, __shfl_xor_sync(0xffffffffu, mx, o));
        float e = (lane<24)? expf(acc-mx) : 0.f;
        float s = e;
        for (int o=16;o;o>>=1) s += __shfl_xor_sync(0xffffffffu, s, o);
        if (lane<24) g_eattn[n*24+lane] = e/s;
    }
}

// ---------------- query LSTMs ----------------
__global__ void q_step0(){
    int idx = blockIdx.x*blockDim.x + threadIdx.x;
    if (idx >= 6*BQ*HID) return;
    int pr = idx/4096; int rem = idx&4095; int b = rem>>7; int u = rem&127;
    float4 P = *(const float4*)(g_Pq + (pr<<14) + (b<<9) + (u<<2));
    float cn = hsigm(P.x)*htanh(P.z);
    g_qc[idx] = cn;
    g_qh[pr*3*4096 + rem] = hsigm(P.w)*htanh(cn);
}

__global__ __launch_bounds__(256) void q_step(int s){
    int pr = blockIdx.y;
    int cb = blockIdx.x<<6;
    const float* h_in = g_qh + (pr*3 + s-1)*4096;
    float* h_out      = g_qh + (pr*3 + s)*4096;
    __shared__ float As[16][36];
    __shared__ float Bs[16][68];
    int tid=threadIdx.x;
    int ty=tid>>4, tx=tid&15;
    const float* Wp = g_Wqperm + (pr<<16);
    float acc[2][4] = {};
    int lrA = tid>>3; int kqA = (tid&7)<<1;
    int lrB = tid>>2; int kqB = (tid&3)<<2;
    for (int kb=0;kb<128;kb+=16){
        float2 a2 = *(const float2*)(h_in + (lrA<<7) + kb + kqA);
        float4 b4 = *(const float4*)(Wp + ((cb+lrB)<<7) + kb + kqB);
        As[kqA+0][lrA]=a2.x; As[kqA+1][lrA]=a2.y;
        Bs[kqB+0][lrB]=b4.x; Bs[kqB+1][lrB]=b4.y; Bs[kqB+2][lrB]=b4.z; Bs[kqB+3][lrB]=b4.w;
        __syncthreads();
        #pragma unroll
        for (int k=0;k<16;k++){
            float a0=As[k][(ty<<1)], a1=As[k][(ty<<1)+1];
            float4 b=*(const float4*)&Bs[k][tx<<2];
            acc[0][0]+=a0*b.x; acc[0][1]+=a0*b.y; acc[0][2]+=a0*b.z; acc[0][3]+=a0*b.w;
            acc[1][0]+=a1*b.x; acc[1][1]+=a1*b.y; acc[1][2]+=a1*b.z; acc[1][3]+=a1*b.w;
        }
        __syncthreads();
    }
    int u = (cb>>2)+tx;
    #pragma unroll
    for (int i=0;i<2;i++){
        int b = (ty<<1)+i;
        float4 P = *(const float4*)(g_Pq + (pr<<14) + (b<<9) + cb + (tx<<2));
        float ig=hsigm(acc[i][0]+P.x), fg=hsigm(acc[i][1]+P.y);
        float gg=htanh(acc[i][2]+P.z), og=hsigm(acc[i][3]+P.w);
        int ci = pr*4096 + (b<<7) + u;
        float cn = fg*g_qc[ci] + ig*gg;
        g_qc[ci]=cn;
        h_out[(b<<7)+u]=og*htanh(cn);
    }
}

__global__ void q_attn_kernel(const float* __restrict__ W, const float* __restrict__ bias){
    __shared__ float Ws[8192];
    int tid=threadIdx.x;
    for (int i=tid;i<8192;i+=256) Ws[i]=0.f;
    __syncthreads();
    for (int i=tid;i<25*256;i+=256){ int o=i>>8,k=i&255; Ws[(k<<5)+o]=W[i]; }
    __syncthreads();
    int lane=tid&31;
    int gw=(blockIdx.x<<3)+(tid>>5);
    if (gw>=288) return;
    int b=gw&31, rt=gw>>5; int r=rt/3, t=rt%3;
    const float* hf = g_qh + ((r*2  )*3 + t    )*4096 + (b<<7);
    const float* hb = g_qh + ((r*2+1)*3 + (2-t))*4096 + (b<<7);
    float acc = (lane<25)? bias[lane] : -1e30f;
    for (int k=0;k<128;k++) acc += hf[k]*Ws[(k<<5)+lane];
    for (int k=0;k<128;k++) acc += hb[k]*Ws[((k+128)<<5)+lane];
    float mx=acc;
    for (int o=16;o;o>>=1) mx=fmaxf(mx,__shfl_xor_sync(0xffffffffu,mx,o));
    float e=(lane<25)?expf(acc-mx):0.f;
    float s=e;
    for (int o=16;o;o>>=1) s+=__shfl_xor_sync(0xffffffffu,s,o);
    if (lane<25) g_qattn[rt*800 + b*25 + lane] = e/s;
}

// ---------------- propagation (CSR gather + fused colsum) ----------------
__global__ void init_sums(){
    int i = threadIdx.x;
    if (i<96){ g_sumsA[i]=1.f; g_sumsB[i]=0.f; }
}

__global__ __launch_bounds__(256) void csr_step(int ab, int t, int t0flag,
                                                const int* __restrict__ heads){
    int r = blockIdx.y;
    __shared__ float qs[800];
    const float* qa = g_qattn + (r*3+t)*800;
    for (int i=threadIdx.x;i<800;i+=256) qs[i]=qa[i];
    __syncthreads();
    const float* inb  = (ab ? g_bufB : g_bufA) + r*NENT*BQ;
    float*       outb = (ab ? g_bufA : g_bufB) + r*NENT*BQ;
    const float* sums =  ab ? g_sumsB : g_sumsA;
    float*       osum =  ab ? g_sumsA : g_sumsB;
    int lane = threadIdx.x&31, wid = threadIdx.x>>5;
    float inv = __fdividef(1.f, fmaxf(1e-20f, sums[r*32+lane]));
    float qlast = qs[lane*25+24];
    int hb = t0flag ? heads[lane] : 0;
    float csum = 0.f;
    int n0 = (blockIdx.x<<6) + (wid<<3);
    #pragma unroll 1
    for (int j=0;j<8;j++){
        int n = n0+j;
        if (n < NENT){
            float acc;
            int s0 = g_offs[n], s1 = g_offs[n+1];
            if (t0flag){
                acc = qlast * ((hb==n)? 1.f : 0.f);
                for (int i=s0;i<s1;i++){
                    int2 en = g_csr[i];
                    float val = qs[lane*25 + (en.x>>17)] * __int_as_float(en.y);
                    acc += ((en.x & 0x1FFFF)==hb) ? val : 0.f;
                }
            } else {
                acc = qlast * inb[(n<<5)+lane];
                int i = s0;
                // 4-wide batching: 4 independent row gathers in flight
                for (; i+4<=s1; i+=4){
                    int2 e0=g_csr[i], e1=g_csr[i+1], e2=g_csr[i+2], e3=g_csr[i+3];
                    float v0 = inb[((e0.x & 0x1FFFF)<<5) + lane];
                    float v1 = inb[((e1.x & 0x1FFFF)<<5) + lane];
                    float v2 = inb[((e2.x & 0x1FFFF)<<5) + lane];
                    float v3 = inb[((e3.x & 0x1FFFF)<<5) + lane];
                    acc += qs[lane*25 + (e0.x>>17)] * __int_as_float(e0.y) * v0;
                    acc += qs[lane*25 + (e1.x>>17)] * __int_as_float(e1.y) * v1;
                    acc += qs[lane*25 + (e2.x>>17)] * __int_as_float(e2.y) * v2;
                    acc += qs[lane*25 + (e3.x>>17)] * __int_as_float(e3.y) * v3;
                }
                for (; i<s1; i++){
                    int2 en = g_csr[i];
                    float val = qs[lane*25 + (en.x>>17)] * __int_as_float(en.y);
                    acc += val * inb[((en.x & 0x1FFFF)<<5) + lane];
                }
            }
            float v = acc*inv;
            outb[(n<<5)+lane] = v;
            csum += v;
        }
    }
    __shared__ float sh[8][32];
    sh[wid][lane]=csum;
    __syncthreads();
    if (wid==0){
        float s=0.f;
        #pragma unroll
        for (int i=0;i<8;i++) s+=sh[i][lane];
        atomicAdd(&osum[r*32+lane], s);
    }
}

__global__ void zero_sums(int sel){
    if (threadIdx.x < 96) (sel ? g_sumsB : g_sumsA)[threadIdx.x] = 0.f;
}

__global__ void trans_out(float* __restrict__ out){
    __shared__ float tile[32][33];
    __shared__ float invs[96];
    int tx=threadIdx.x, ty=threadIdx.y;
    if (ty<3) invs[ty*32+tx] = __fdividef(1.f, fmaxf(1e-20f, g_sumsB[ty*32+tx]));
    __syncthreads();
    int n0=blockIdx.x<<5;
    int n=n0+ty;
    float v = 0.f;
    if (n<NENT){
        int i = (n<<5)+tx;
        v = g_bufB[i]*invs[tx] + g_bufB[NENT*BQ+i]*invs[32+tx] + g_bufB[2*NENT*BQ+i]*invs[64+tx];
    }
    tile[ty][tx] = v;
    __syncthreads();
    int nn=n0+tx;
    if (nn<NENT) out[ty*NENT+nn] = tile[tx][ty];
}

// ---------------- host ----------------
extern "C" void kernel_launch(void* const* d_in, const int* in_sizes, int n_in,
                              void* d_out, int out_size){
    const int*   queries=(const int*)d_in[0];
    const int*   heads  =(const int*)d_in[1];
    const int*   rels   =(const int*)d_in[2];
    const int*   t_heads=(const int*)d_in[3];
    const int*   t_tails=(const int*)d_in[4];
    const int*   degs   =(const int*)d_in[5];
    const float* qemb=(const float*)d_in[6];
    const float* eemb=(const float*)d_in[7];
    const float* qWih=(const float*)d_in[8];
    const float* qWhh=(const float*)d_in[9];
    const float* qbih=(const float*)d_in[10];
    const float* qbhh=(const float*)d_in[11];
    const float* eWih=(const float*)d_in[12];
    const float* eWhh=(const float*)d_in[13];
    const float* ebih=(const float*)d_in[14];
    const float* ebhh=(const float*)d_in[15];
    const float* qlW=(const float*)d_in[16];
    const float* qlb=(const float*)d_in[17];
    const float* elW=(const float*)d_in[18];
    const float* elb=(const float*)d_in[19];
    float* out=(float*)d_out;

    static cudaStream_t sB = 0, sC = 0;
    static cudaEvent_t ePrep = 0, eScatter = 0, eQ = 0, eFork = 0;
    if (!sB){
        cudaStreamCreateWithFlags(&sB, cudaStreamNonBlocking);
        cudaStreamCreateWithFlags(&sC, cudaStreamNonBlocking);
        cudaEventCreateWithFlags(&ePrep, cudaEventDisableTiming);
        cudaEventCreateWithFlags(&eScatter, cudaEventDisableTiming);
        cudaEventCreateWithFlags(&eQ, cudaEventDisableTiming);
        cudaEventCreateWithFlags(&eFork, cudaEventDisableTiming);
        cudaFuncSetAttribute(ent_fused, cudaFuncAttributeMaxDynamicSharedMemorySize, DSMEM);
    }

    // fork side streams off the capture-origin (default) stream
    cudaEventRecord(eFork, 0);
    cudaStreamWaitEvent(sB, eFork, 0);

    // stream B: CSR build (depends only on inputs)
    zero_cnt<<<(NENT+255)/256,256,0,sB>>>();
    count_k<<<(NEDGE+255)/256,256,0,sB>>>(t_heads, t_tails);
    scan1<<<NB_SCAN,1024,0,sB>>>();
    scan2<<<1,64,0,sB>>>();
    scan3<<<(NENT+255)/256,256,0,sB>>>();
    scatter_k<<<(NEDGE+255)/256,256,0,sB>>>(rels, t_heads, t_tails);
    cudaEventRecord(eScatter, sB);

    // stream 0: prep -> ent_fused -> ent_attn
    prep_kernel<<<(PREP_TOT+255)/256,256>>>(eWih,eWhh,ebih,ebhh,eemb,
                                            qWih,qWhh,qbih,qbhh,qemb,queries);
    cudaEventRecord(ePrep, 0);
    cudaStreamWaitEvent(sC, ePrep, 0);

    // stream C: query BiLSTMs (depend on prep only)
    q_step0<<<96,256,0,sC>>>();
    q_step<<<dim3(8,6),256,0,sC>>>(1);
    q_step<<<dim3(8,6),256,0,sC>>>(2);
    q_attn_kernel<<<36,256,0,sC>>>(qlW, qlb);
    cudaEventRecord(eQ, sC);

    ent_fused<<<dim3(MTILES,2),512,DSMEM>>>(degs);
    ent_attn_kernel<<<1024,256>>>(elW, elb);

    // join: fill_w needs scatter + ent_attn; csr_step needs q_attn
    cudaStreamWaitEvent(0, eScatter, 0);
    fill_w<<<(NCSR+255)/256,256>>>();
    cudaStreamWaitEvent(0, eQ, 0);

    init_sums<<<1,128>>>();
    csr_step<<<dim3(782,3),256>>>(0, 0, 1, heads);
    zero_sums<<<1,128>>>(0);
    csr_step<<<dim3(782,3),256>>>(1, 1, 0, heads);
    zero_sums<<<1,128>>>(1);
    csr_step<<<dim3(782,3),256>>>(0, 2, 0, heads);
    trans_out<<<1563,dim3(32,32)>>>(out);
}